// round 8
// baseline (speedup 1.0000x reference)
#include <cuda_runtime.h>
#include <cuda_fp16.h>
#include <math.h>

#define B 128
#define S 400
#define H 256
#define E 128
#define V 50000
#define OOV 50
#define TWOH 512
#define VO (V + OOV)

#define OFF_HT   (B * VO)
#define OFF_CT   (OFF_HT + B * H)
#define OFF_CTX  (OFF_CT + B * H)
#define OFF_AT   (OFF_CTX + B * TWOH)
#define OFF_GP   (OFF_AT + B * S)
#define OFF_COV  (OFF_GP + B)

__device__ float g_decbase[B * TWOH];
__device__ float g_gpart[B];
__device__ float g_et[B * S];
__device__ float g_hidden[B * H];
__device__ float g_logits[(size_t)B * V];
__device__ float g_psum[B];
__device__ float g_ctxpart[B * 4 * TWOH];
// Wh pre-split fp16 hi, k-pair packed, chunked: [16 chunks][512 n][16 kp]
__device__ unsigned g_WhHi[16 * 512 * 16];

__device__ __forceinline__ float sigf(float x) { return 1.0f / (1.0f + expf(-x)); }

__device__ __forceinline__ float wred(float a) {
    a += __shfl_xor_sync(0xffffffffu, a, 16);
    a += __shfl_xor_sync(0xffffffffu, a, 8);
    a += __shfl_xor_sync(0xffffffffu, a, 4);
    a += __shfl_xor_sync(0xffffffffu, a, 2);
    a += __shfl_xor_sync(0xffffffffu, a, 1);
    return a;
}

__device__ __forceinline__ void splitpack(float x, float y, unsigned& hi, unsigned& lo) {
    __half hx = __float2half_rn(x), hy = __float2half_rn(y);
    __half lx = __float2half_rn(x - __half2float(hx));
    __half ly = __float2half_rn(y - __half2float(hy));
    hi = ((unsigned)__half_as_ushort(hy) << 16) | (unsigned)__half_as_ushort(hx);
    lo = ((unsigned)__half_as_ushort(ly) << 16) | (unsigned)__half_as_ushort(lx);
}

// fp16 mma, fp32 accumulate
__device__ __forceinline__ void mma16(float c[4], const unsigned a[4], unsigned b0, unsigned b1) {
    asm("mma.sync.aligned.m16n8k16.row.col.f32.f16.f16.f32 "
        "{%0,%1,%2,%3}, {%4,%5,%6,%7}, {%8,%9}, {%0,%1,%2,%3};"
        : "+f"(c[0]), "+f"(c[1]), "+f"(c[2]), "+f"(c[3])
        : "r"(a[0]), "r"(a[1]), "r"(a[2]), "r"(a[3]), "r"(b0), "r"(b1));
}
// fp16 mma, fp16 accumulate (hypothesized double rate)
__device__ __forceinline__ void mma16h(unsigned c[2], const unsigned a[4], unsigned b0, unsigned b1) {
    asm("mma.sync.aligned.m16n8k16.row.col.f16.f16.f16.f16 "
        "{%0,%1}, {%2,%3,%4,%5}, {%6,%7}, {%0,%1};"
        : "+r"(c[0]), "+r"(c[1])
        : "r"(a[0]), "r"(a[1]), "r"(a[2]), "r"(a[3]), "r"(b0), "r"(b1));
}

__device__ __forceinline__ void cpa16(unsigned dst, const void* src) {
    asm volatile("cp.async.cg.shared.global [%0], [%1], 16;" :: "r"(dst), "l"(src));
}
#define CP_COMMIT asm volatile("cp.async.commit_group;" ::: "memory")
#define CP_WAIT0  asm volatile("cp.async.wait_group 0;" ::: "memory")

// ---------------------------------------------------------------------------
// K0: pre-split Wh into fp16 hi, k-pair packed; zero g_psum. grid=(512), 256thr.
// ---------------------------------------------------------------------------
__global__ void k0_wh(const float* __restrict__ Wh)
{
    int idx = blockIdx.x * 256 + threadIdx.x;
    int n = idx >> 8;
    int kpg = idx & 255;
    int k = kpg * 2;
    int c = k >> 5, kp = (k & 31) >> 1;
    float2 v = *(const float2*)(Wh + (size_t)n * TWOH + k);
    unsigned hi, lo;
    splitpack(v.x, v.y, hi, lo);
    g_WhHi[(c * 512 + n) * 16 + kp] = hi;
    if (blockIdx.x == 0 && threadIdx.x < B) g_psum[threadIdx.x] = 0.f;
}

// ---------------------------------------------------------------------------
// K1: embedding + input proj + LSTM + decbase + gen_p partial. grid=(B), 256thr.
// ---------------------------------------------------------------------------
__global__ void k1_lstm(
    const int* __restrict__ idx, const float* __restrict__ h0, const float* __restrict__ c0,
    const float* __restrict__ ctxv, const float* __restrict__ emb,
    const float* __restrict__ Wi, const float* __restrict__ bi,
    const float* __restrict__ W_ih, const float* __restrict__ W_hh,
    const float* __restrict__ b_ih, const float* __restrict__ b_hh,
    const float* __restrict__ att_ws, const float* __restrict__ att_bc,
    const float* __restrict__ gp_ws, const float* __restrict__ gp_bs,
    const float* __restrict__ gp_wx, const float* __restrict__ gp_bx,
    const float* __restrict__ gp_bh,
    float* __restrict__ out)
{
    const int b = blockIdx.x;
    const int tid = threadIdx.x;
    const int w = tid >> 5, lane = tid & 31;

    __shared__ float s_in[TWOH + E];
    __shared__ float s_x[E];
    __shared__ float s_h0[H];
    __shared__ float s_gates[4 * H];
    __shared__ float s_st[TWOH];
    __shared__ float s_red[256];

    for (int k = tid; k < TWOH; k += 256) s_in[k] = ctxv[b * TWOH + k];
    if (tid < E) s_in[TWOH + tid] = emb[(size_t)idx[b] * E + tid];
    s_h0[tid] = h0[b * H + tid];
    __syncthreads();

    for (int o = w * 16; o < (w + 1) * 16; o++) {
        const float* wr = Wi + (size_t)o * (TWOH + E);
        float a = 0.f;
        for (int k = lane; k < TWOH + E; k += 32) a += wr[k] * s_in[k];
        a = wred(a);
        if (lane == 0) s_x[o] = a + bi[o];
    }
    __syncthreads();

    for (int o = w * 128; o < (w + 1) * 128; o++) {
        const float* wi_ = W_ih + (size_t)o * E;
        const float* wh_ = W_hh + (size_t)o * H;
        float a = 0.f;
        for (int k = lane; k < E; k += 32) a += wi_[k] * s_x[k];
        for (int k = lane; k < H; k += 32) a += wh_[k] * s_h0[k];
        a = wred(a);
        if (lane == 0) s_gates[o] = a + b_ih[o] + b_hh[o];
    }
    __syncthreads();

    {
        float ig = sigf(s_gates[tid]);
        float fg = sigf(s_gates[H + tid]);
        float gg = tanhf(s_gates[2 * H + tid]);
        float og = sigf(s_gates[3 * H + tid]);
        float c = fg * c0[b * H + tid] + ig * gg;
        float h = og * tanhf(c);
        out[OFF_HT + b * H + tid] = h;
        out[OFF_CT + b * H + tid] = c;
        s_st[tid] = h;
        s_st[H + tid] = c;
    }
    __syncthreads();

    for (int o = w * 64; o < (w + 1) * 64; o++) {
        const float* wr = att_ws + (size_t)o * TWOH;
        float a = 0.f;
        for (int k = lane; k < TWOH; k += 32) a += wr[k] * s_st[k];
        a = wred(a);
        if (lane == 0) g_decbase[b * TWOH + o] = a + att_bc[o];
    }

    float p = 0.f;
    for (int k = tid; k < TWOH; k += 256) p += gp_ws[k] * s_st[k];
    if (tid < E) p += gp_wx[tid] * s_x[tid];
    s_red[tid] = p;
    __syncthreads();
    for (int off = 128; off > 0; off >>= 1) {
        if (tid < off) s_red[tid] += s_red[tid + off];
        __syncthreads();
    }
    if (tid == 0) g_gpart[b] = s_red[0] + gp_bs[0] + gp_bx[0] + gp_bh[0];
}

// ---------------------------------------------------------------------------
// K2: attention scores. hi-product fp32-acc mma + lo-product fp16-acc mma.
// B staged via cp.async (register-free). Double-buffered.
// Block: 64 rows x 512 n, K=512 in 16 chunks of 32. 512thr = 16 warps (2m x 8n).
// ---------------------------------------------------------------------------
#define K2P 20
#define K2_BUF 51200
#define K2_AH 0
#define K2_AL 5120
#define K2_BH 10240
#define K2_SV  102400
#define K2_SWC 104448
#define K2_SDB 106496
#define K2_EP  110592
#define K2_SMEM 112640

__global__ void __launch_bounds__(512, 1) k2_mma(
    const float* __restrict__ EO,
    const float* __restrict__ att_wc, const float* __restrict__ att_v,
    const float* __restrict__ coverage, const int* __restrict__ mask)
{
    extern __shared__ char smem[];
    float* sv  = (float*)(smem + K2_SV);
    float* swc = (float*)(smem + K2_SWC);
    float* sdb = (float*)(smem + K2_SDB);
    float* ep  = (float*)(smem + K2_EP);

    const int tid = threadIdx.x;
    const int w = tid >> 5, lane = tid & 31;
    const int g = lane >> 2, t = lane & 3;
    const int wm = w & 1, wn = w >> 1;
    const int row0 = blockIdx.x * 64;
    const int b0 = row0 / S;
    const int b1e = (row0 + 63) / S;

    sv[tid] = att_v[tid];
    swc[tid] = att_wc[tid];
    sdb[tid] = g_decbase[b0 * TWOH + tid];
    sdb[512 + tid] = g_decbase[b1e * TWOH + tid];

    const int ar = tid >> 3, aq = tid & 7;
    const int bn = tid >> 2, bkq = tid & 3;
    const float* aptr = EO + (size_t)(row0 + ar) * TWOH + aq * 4;

    float c[2][8][4];
    unsigned clo[2][8][2];
    #pragma unroll
    for (int mi = 0; mi < 2; mi++)
        #pragma unroll
        for (int ni = 0; ni < 8; ni++) {
            #pragma unroll
            for (int q = 0; q < 4; q++) c[mi][ni][q] = 0.f;
            clo[mi][ni][0] = 0u; clo[mi][ni][1] = 0u;
        }

    // prologue: chunk 0
    {
        unsigned bdst = (unsigned)__cvta_generic_to_shared(smem + K2_BH);
        #pragma unroll
        for (int i = 0; i < 4; i++)
            cpa16(bdst + (unsigned)(((i * 128 + bn) * K2P + bkq * 4) * 4),
                  g_WhHi + ((size_t)(i * 128 + bn) * 16 + bkq * 4));
        CP_COMMIT;
        float4 av = *(const float4*)(aptr);
        unsigned h0_, l0_, h1_, l1_;
        splitpack(av.x, av.y, h0_, l0_);
        splitpack(av.z, av.w, h1_, l1_);
        *(uint2*)((unsigned*)(smem + K2_AH) + ar * K2P + aq * 2) = make_uint2(h0_, h1_);
        *(uint2*)((unsigned*)(smem + K2_AL) + ar * K2P + aq * 2) = make_uint2(l0_, l1_);
        CP_WAIT0;
    }
    __syncthreads();

    for (int kt = 0; kt < 16; kt++) {
        char* bufc = smem + (kt & 1) * K2_BUF;
        float4 av;
        if (kt < 15) {
            char* bufn = smem + ((kt + 1) & 1) * K2_BUF;
            unsigned bdst = (unsigned)__cvta_generic_to_shared(bufn + K2_BH);
            #pragma unroll
            for (int i = 0; i < 4; i++)
                cpa16(bdst + (unsigned)(((i * 128 + bn) * K2P + bkq * 4) * 4),
                      g_WhHi + ((size_t)((kt + 1) * 512 + i * 128 + bn) * 16 + bkq * 4));
            CP_COMMIT;
            av = *(const float4*)(aptr + (kt + 1) * 32);
        }

        unsigned* AHc = (unsigned*)(bufc + K2_AH);
        unsigned* ALc = (unsigned*)(bufc + K2_AL);
        unsigned* BHc = (unsigned*)(bufc + K2_BH);
        #pragma unroll
        for (int s = 0; s < 2; s++) {
            unsigned af[2][4];
            // hi product (fp32 accumulate)
            #pragma unroll
            for (int mi = 0; mi < 2; mi++) {
                const unsigned* pa = AHc + (wm * 32 + mi * 16 + g) * K2P + s * 8 + t;
                af[mi][0] = pa[0]; af[mi][1] = pa[8 * K2P];
                af[mi][2] = pa[4]; af[mi][3] = pa[8 * K2P + 4];
            }
            #pragma unroll
            for (int ni = 0; ni < 8; ni++) {
                const unsigned* pb = BHc + (wn * 64 + ni * 8 + g) * K2P + s * 8 + t;
                unsigned bh0 = pb[0], bh1 = pb[4];
                #pragma unroll
                for (int mi = 0; mi < 2; mi++)
                    mma16(c[mi][ni], af[mi], bh0, bh1);
            }
            // lo product (fp16 accumulate)
            #pragma unroll
            for (int mi = 0; mi < 2; mi++) {
                const unsigned* pl = ALc + (wm * 32 + mi * 16 + g) * K2P + s * 8 + t;
                af[mi][0] = pl[0]; af[mi][1] = pl[8 * K2P];
                af[mi][2] = pl[4]; af[mi][3] = pl[8 * K2P + 4];
            }
            #pragma unroll
            for (int ni = 0; ni < 8; ni++) {
                const unsigned* pb = BHc + (wn * 64 + ni * 8 + g) * K2P + s * 8 + t;
                unsigned bh0 = pb[0], bh1 = pb[4];
                #pragma unroll
                for (int mi = 0; mi < 2; mi++)
                    mma16h(clo[mi][ni], af[mi], bh0, bh1);
            }
        }

        if (kt < 15) {
            char* bufn = smem + ((kt + 1) & 1) * K2_BUF;
            unsigned h0_, l0_, h1_, l1_;
            splitpack(av.x, av.y, h0_, l0_);
            splitpack(av.z, av.w, h1_, l1_);
            *(uint2*)((unsigned*)(bufn + K2_AH) + ar * K2P + aq * 2) = make_uint2(h0_, h1_);
            *(uint2*)((unsigned*)(bufn + K2_AL) + ar * K2P + aq * 2) = make_uint2(l0_, l1_);
            CP_WAIT0;
        }
        __syncthreads();
    }

    // epilogue: fold lo accum, exact tanh + v-dot, reduce
    #pragma unroll
    for (int mi = 0; mi < 2; mi++) {
        #pragma unroll
        for (int hf = 0; hf < 2; hf++) {
            const int rl = wm * 32 + mi * 16 + hf * 8 + g;
            const int r = row0 + rl;
            const int dbo = (r / S != b0) ? 512 : 0;
            const float cov = coverage[r];
            float acc = 0.f;
            #pragma unroll
            for (int ni = 0; ni < 8; ni++) {
                const int j = wn * 64 + ni * 8 + t * 2;
                __half2 lo2 = *(__half2*)&clo[mi][ni][hf];
                float v0 = c[mi][ni][hf * 2 + 0] + __half2float(lo2.x) + sdb[dbo + j] + cov * swc[j];
                float v1 = c[mi][ni][hf * 2 + 1] + __half2float(lo2.y) + sdb[dbo + j + 1] + cov * swc[j + 1];
                acc += sv[j] * tanhf(v0) + sv[j + 1] * tanhf(v1);
            }
            acc += __shfl_xor_sync(0xffffffffu, acc, 1);
            acc += __shfl_xor_sync(0xffffffffu, acc, 2);
            if (t == 0) ep[rl * 8 + wn] = acc;
        }
    }
    __syncthreads();
    if (tid < 64) {
        float sacc = 0.f;
        #pragma unroll
        for (int q = 0; q < 8; q++) sacc += ep[tid * 8 + q];
        const int r = row0 + tid;
        g_et[r] = (mask[r] == 0) ? -1e30f : sacc;
    }
}

// ---------------------------------------------------------------------------
// K3a: masked softmax over S -> a_t, next_coverage. grid=(B), 512thr.
// ---------------------------------------------------------------------------
__global__ void k3a_softmax(const float* __restrict__ coverage, float* __restrict__ out)
{
    const int b = blockIdx.x;
    const int t = threadIdx.x;
    __shared__ float red[512];

    float e = (t < S) ? g_et[b * S + t] : -1e30f;
    red[t] = e;
    __syncthreads();
    for (int off = 256; off > 0; off >>= 1) {
        if (t < off) red[t] = fmaxf(red[t], red[t + off]);
        __syncthreads();
    }
    const float mx = red[0];
    __syncthreads();

    float ex = (t < S) ? expf(e - mx) : 0.f;
    red[t] = ex;
    __syncthreads();
    for (int off = 256; off > 0; off >>= 1) {
        if (t < off) red[t] += red[t + off];
        __syncthreads();
    }
    const float inv = 1.f / red[0];

    if (t < S) {
        float a = ex * inv;
        out[OFF_AT + b * S + t] = a;
        out[OFF_COV + b * S + t] = coverage[b * S + t] + a;
    }
}

// ---------------------------------------------------------------------------
// K3c: ctx partials. grid=(B*4), 512thr.
// ---------------------------------------------------------------------------
__global__ void k3c_ctxpart(const float* __restrict__ EO, const float* __restrict__ out)
{
    const int blk = blockIdx.x;
    const int b = blk >> 2, q = blk & 3;
    const int t = threadIdx.x;
    __shared__ float sa[100];
    if (t < 100) sa[t] = out[OFF_AT + b * S + q * 100 + t];
    __syncthreads();
    const float* eob = EO + ((size_t)b * S + q * 100) * TWOH;
    float c = 0.f;
    #pragma unroll 10
    for (int s = 0; s < 100; s++) c += sa[s] * eob[(size_t)s * TWOH + t];
    g_ctxpart[(size_t)blk * TWOH + t] = c;
}

// ---------------------------------------------------------------------------
// K3d: combine ctx partials + gen_p. grid=(B), 512thr.
// ---------------------------------------------------------------------------
__global__ void k3d_ctx(const float* __restrict__ gp_wh, float* __restrict__ out)
{
    const int b = blockIdx.x;
    const int t = threadIdx.x;
    __shared__ float red[512];
    float c = g_ctxpart[(size_t)(b * 4 + 0) * TWOH + t]
            + g_ctxpart[(size_t)(b * 4 + 1) * TWOH + t]
            + g_ctxpart[(size_t)(b * 4 + 2) * TWOH + t]
            + g_ctxpart[(size_t)(b * 4 + 3) * TWOH + t];
    out[OFF_CTX + b * TWOH + t] = c;
    red[t] = gp_wh[t] * c;
    __syncthreads();
    for (int off = 256; off > 0; off >>= 1) {
        if (t < off) red[t] += red[t + off];
        __syncthreads();
    }
    if (t == 0) out[OFF_GP + b] = sigf(red[0] + g_gpart[b]);
}

// ---------------------------------------------------------------------------
// K3b: hidden = relu(out_w1 @ [h_t, ctx] + b1), tiled 64x64. grid=(4,2), 256thr.
// ---------------------------------------------------------------------------
__global__ void k3b_hidden(
    const float* __restrict__ out_w1, const float* __restrict__ out_b1,
    const float* __restrict__ out)
{
    __shared__ __align__(16) float As[16][68];
    __shared__ __align__(16) float Ws[16][68];

    const int tid = threadIdx.x;
    const int tx = tid & 15, ty = tid >> 4;
    const int rl = tid >> 2, kq = tid & 3;
    const int m0 = blockIdx.y * 64;
    const int n0 = blockIdx.x * 64;

    float acc[4][4];
    #pragma unroll
    for (int a = 0; a < 4; a++)
        #pragma unroll
        for (int c = 0; c < 4; c++) acc[a][c] = 0.f;

    for (int kt = 0; kt < 48; kt++) {
        const int k = kt * 16 + kq * 4;
        const int m = m0 + rl;
        float4 av = (k < H)
            ? *(const float4*)(out + OFF_HT + m * H + k)
            : *(const float4*)(out + OFF_CTX + m * TWOH + (k - H));
        float4 wv = *(const float4*)(out_w1 + (size_t)(n0 + rl) * (H + TWOH) + k);
        __syncthreads();
        As[kq * 4 + 0][rl] = av.x; As[kq * 4 + 1][rl] = av.y;
        As[kq * 4 + 2][rl] = av.z; As[kq * 4 + 3][rl] = av.w;
        Ws[kq * 4 + 0][rl] = wv.x; Ws[kq * 4 + 1][rl] = wv.y;
        Ws[kq * 4 + 2][rl] = wv.z; Ws[kq * 4 + 3][rl] = wv.w;
        __syncthreads();
        #pragma unroll
        for (int kk = 0; kk < 16; kk++) {
            float ar[4], wr[4];
            *(float4*)ar = *(const float4*)&As[kk][ty * 4];
            *(float4*)wr = *(const float4*)&Ws[kk][tx * 4];
            #pragma unroll
            for (int mi = 0; mi < 4; mi++)
                #pragma unroll
                for (int jj = 0; jj < 4; jj++)
                    acc[mi][jj] += ar[mi] * wr[jj];
        }
    }

    #pragma unroll
    for (int mi = 0; mi < 4; mi++) {
        const int m = m0 + ty * 4 + mi;
        #pragma unroll
        for (int jj = 0; jj < 4; jj++) {
            const int o = n0 + tx * 4 + jj;
            g_hidden[m * H + o] = fmaxf(acc[mi][jj] + out_b1[o], 0.f);
        }
    }
}

// ---------------------------------------------------------------------------
// K4: logits GEMM + fused vocab sum-exp (no max shift; logits are O(1)).
// fp16 two-product, double-buffered. Block 128m x 256n, 512thr (4m x 4n warps).
// ---------------------------------------------------------------------------
#define K2P 20
#define K4_BUF 40960
#define K4_AH 0
#define K4_AL 10240
#define K4_BH 20480
#define K4_SMEM 81920

__global__ void __launch_bounds__(512, 1) k4_mma(
    const float* __restrict__ W2, const float* __restrict__ b2)
{
    extern __shared__ char smem[];

    const int tid = threadIdx.x;
    const int w = tid >> 5, lane = tid & 31;
    const int g = lane >> 2, t = lane & 3;
    const int wm = w & 3, wn = w >> 2;
    const int j0 = blockIdx.x * 256;

    const int ar = tid >> 3, aq = tid & 7;
    const int br = tid >> 3, bq = tid & 7;

    float c[2][8][4];
    #pragma unroll
    for (int mi = 0; mi < 2; mi++)
        #pragma unroll
        for (int ni = 0; ni < 8; ni++)
            #pragma unroll
            for (int q = 0; q < 4; q++) c[mi][ni][q] = 0.f;

    float4 avv[2], bvv[4];

    #pragma unroll
    for (int i = 0; i < 2; i++)
        avv[i] = *(const float4*)(g_hidden + (size_t)(i * 64 + ar) * H + aq * 4);
    #pragma unroll
    for (int i = 0; i < 4; i++) {
        int j = j0 + i * 64 + br;
        bvv[i] = (j < V) ? *(const float4*)(W2 + (size_t)j * H + bq * 4)
                         : make_float4(0.f, 0.f, 0.f, 0.f);
    }
    {
        unsigned* AHp = (unsigned*)(smem + K4_AH);
        unsigned* ALp = (unsigned*)(smem + K4_AL);
        unsigned* BHp = (unsigned*)(smem + K4_BH);
        #pragma unroll
        for (int i = 0; i < 2; i++) {
            unsigned h0_, l0_, h1_, l1_;
            splitpack(avv[i].x, avv[i].y, h0_, l0_);
            splitpack(avv[i].z, avv[i].w, h1_, l1_);
            *(uint2*)(AHp + (i * 64 + ar) * K2P + aq * 2) = make_uint2(h0_, h1_);
            *(uint2*)(ALp + (i * 64 + ar) * K2P + aq * 2) = make_uint2(l0_, l1_);
        }
        #pragma unroll
        for (int i = 0; i < 4; i++) {
            unsigned h0_, l0_, h1_, l1_;
            splitpack(bvv[i].x, bvv[i].y, h0_, l0_);
            splitpack(bvv[i].z, bvv[i].w, h1_, l1_);
            *(uint2*)(BHp + (i * 64 + br) * K2P + bq * 2) = make_uint2(h0_, h1_);
        }
    }
    __syncthreads();

    for (int kt = 0; kt < 8; kt++) {
        char* bufc = smem + (kt & 1) * K4_BUF;
        if (kt < 7) {
            const int k0 = (kt + 1) * 32;
            #pragma unroll
            for (int i = 0; i < 2; i++)
                avv[i] = *(const float4*)(g_hidden + (size_t)(i * 64 + ar) * H + k0 + aq * 4);
            #pragma unroll
            for (int i = 0; i < 4; i++) {
                int j = j0 + i * 64 + br;
                bvv[i] = (j < V) ? *(const float4*)(W2 + (size_t)j * H + k0 + bq * 4)
                                 : make_float4(0.f, 0.f, 0.f, 0.f);
            }
        }

        unsigned* AHc = (unsigned*)(bufc + K4_AH);
        unsigned* ALc = (unsigned*)(bufc + K4_AL);
        unsigned* BHc = (unsigned*)(bufc + K4_BH);
        #pragma unroll
        for (int s = 0; s < 2; s++) {
            unsigned ah[2][4], al[2][4];
            #pragma unroll
            for (int mi = 0; mi < 2; mi++) {
                const unsigned* pa = AHc + (wm * 32 + mi * 16 + g) * K2P + s * 8 + t;
                ah[mi][0] = pa[0]; ah[mi][1] = pa[8 * K2P];
                ah[mi][2] = pa[4]; ah[mi][3] = pa[8 * K2P + 4];
                const unsigned* pl = ALc + (wm * 32 + mi * 16 + g) * K2P + s * 8 + t;
                al[mi][0] = pl[0]; al[mi][1] = pl[8 * K2P];
                al[mi][2] = pl[4]; al[mi][3] = pl[8 * K2P + 4];
            }
            #pragma unroll
            for (int ni = 0; ni < 8; ni++) {
                const unsigned* pb = BHc + (wn * 64 + ni * 8 + g) * K2P + s * 8 + t;
                unsigned bh0 = pb[0], bh1 = pb[4];
                #pragma unroll
                for (int mi = 0; mi < 2; mi++) {
                    mma16(c[mi][ni], ah[mi], bh0, bh1);
                    mma16(c[mi][ni], al[mi], bh0, bh1);
                }
            }
        }

        if (kt < 7) {
            char* bufn = smem + ((kt + 1) & 1) * K4_BUF;
            unsigned* AHn = (unsigned*)(bufn + K4_AH);
            unsigned* ALn = (unsigned*)(bufn + K4_AL);
            unsigned* BHn = (unsigned*)(bufn + K4_BH);
            #pragma unroll
            for (int i = 0; i < 2; i++) {
                unsigned h0_, l0_, h1_, l1_;
                splitpack(avv[i].x, avv[i].y, h0_, l0_);
                splitpack(avv[i].z, avv[i].w, h1_, l1_);
                *(uint2*)(AHn + (i * 64 + ar) * K2P + aq * 2) = make_uint2(h0_, h1_);
                *(uint2*)(ALn + (i * 64 + ar) * K2P + aq * 2) = make_uint2(l0_, l1_);
            }
            #pragma unroll
            for (int i = 0; i < 4; i++) {
                unsigned h0_, l0_, h1_, l1_;
                splitpack(bvv[i].x, bvv[i].y, h0_, l0_);
                splitpack(bvv[i].z, bvv[i].w, h1_, l1_);
                *(uint2*)(BHn + (i * 64 + br) * K2P + bq * 2) = make_uint2(h0_, h1_);
            }
        }
        __syncthreads();
    }

    // epilogue: write logits + per-row partial sum of exp(logit)
    float* ssum = (float*)smem;   // reuse (all mainloop smem reads done)
    #pragma unroll
    for (int mi = 0; mi < 2; mi++) {
        #pragma unroll
        for (int hf = 0; hf < 2; hf++) {
            const int r = wm * 32 + mi * 16 + hf * 8 + g;
            float ps = 0.f;
            #pragma unroll
            for (int ni = 0; ni < 8; ni++) {
                const int j = j0 + wn * 64 + ni * 8 + t * 2;
                if (j < V) {
                    float o0 = c[mi][ni][hf * 2 + 0] + b2[j];
                    float o1 = c[mi][ni][hf * 2 + 1] + b2[j + 1];
                    *(float2*)(g_logits + (size_t)r * V + j) = make_float2(o0, o1);
                    ps += expf(o0) + expf(o1);
                }
            }
            ps += __shfl_xor_sync(0xffffffffu, ps, 1);
            ps += __shfl_xor_sync(0xffffffffu, ps, 2);
            if (t == 0) ssum[r * 4 + wn] = ps;
        }
    }
    __syncthreads();
    if (tid < 128) {
        float s2 = ssum[tid * 4] + ssum[tid * 4 + 1] + ssum[tid * 4 + 2] + ssum[tid * 4 + 3];
        atomicAdd(&g_psum[tid], s2);
    }
}

// ---------------------------------------------------------------------------
// K5b: final_dist = exp(logit)/sumexp * gen_p, zero OOV tail.
// ---------------------------------------------------------------------------
__global__ void k5b_final(float* __restrict__ out)
{
    const int i = blockIdx.x * 256 + threadIdx.x;
    if (i >= B * VO) return;
    const int b = i / VO;
    const int c = i - b * VO;
    float v = 0.f;
    if (c < V) {
        const float gp = out[OFF_GP + b];
        v = expf(g_logits[(size_t)b * V + c]) * (1.f / g_psum[b]) * gp;
    }
    out[i] = v;
}

__global__ void k5c_scatter(const int* __restrict__ ewo, float* __restrict__ out)
{
    const int i = blockIdx.x * 256 + threadIdx.x;
    if (i >= B * S) return;
    const int b = i / S;
    const float gp = out[OFF_GP + b];
    const float a = out[OFF_AT + i];
    atomicAdd(out + (size_t)b * VO + ewo[i], a * (1.f - gp));
}

// ---------------------------------------------------------------------------
extern "C" void kernel_launch(void* const* d_in, const int* in_sizes, int n_in,
                              void* d_out, int out_size)
{
    const int*   idx      = (const int*)  d_in[0];
    const float* h0       = (const float*)d_in[1];
    const float* c0       = (const float*)d_in[2];
    const float* EO       = (const float*)d_in[3];
    const int*   emask    = (const int*)  d_in[4];
    const float* ctxv     = (const float*)d_in[5];
    const int*   ewo      = (const int*)  d_in[7];
    const float* coverage = (const float*)d_in[8];
    const float* emb      = (const float*)d_in[9];
    const float* Wi       = (const float*)d_in[10];
    const float* bi       = (const float*)d_in[11];
    const float* W_ih     = (const float*)d_in[12];
    const float* W_hh     = (const float*)d_in[13];
    const float* b_ih     = (const float*)d_in[14];
    const float* b_hh     = (const float*)d_in[15];
    const float* att_wh   = (const float*)d_in[16];
    const float* att_ws   = (const float*)d_in[17];
    const float* att_wc   = (const float*)d_in[18];
    const float* att_bc   = (const float*)d_in[19];
    const float* att_v    = (const float*)d_in[20];
    const float* gp_wh    = (const float*)d_in[21];
    const float* gp_bh    = (const float*)d_in[22];
    const float* gp_ws    = (const float*)d_in[23];
    const float* gp_bs    = (const float*)d_in[24];
    const float* gp_wx    = (const float*)d_in[25];
    const float* gp_bx    = (const float*)d_in[26];
    const float* out_w1   = (const float*)d_in[27];
    const float* out_b1   = (const float*)d_in[28];
    const float* out_w2   = (const float*)d_in[29];
    const float* out_b2   = (const float*)d_in[30];
    float* out = (float*)d_out;

    static int attr_done = 0;
    if (!attr_done) {
        cudaFuncSetAttribute(k2_mma, cudaFuncAttributeMaxDynamicSharedMemorySize, K2_SMEM);
        cudaFuncSetAttribute(k4_mma, cudaFuncAttributeMaxDynamicSharedMemorySize, K4_SMEM);
        attr_done = 1;
    }

    k0_wh<<<512, 256>>>(att_wh);
    k1_lstm<<<B, 256>>>(idx, h0, c0, ctxv, emb, Wi, bi, W_ih, W_hh, b_ih, b_hh,
                        att_ws, att_bc, gp_ws, gp_bs, gp_wx, gp_bx, gp_bh, out);
    k2_mma<<<(B * S) / 64, 512, K2_SMEM>>>(EO, att_wc, att_v, coverage, emask);
    k3a_softmax<<<B, 512>>>(coverage, out);
    k3c_ctxpart<<<B * 4, 512>>>(EO, out);
    k3d_ctx<<<B, 512>>>(gp_wh, out);
    {
        dim3 g3b(4, 2);
        k3b_hidden<<<g3b, 256>>>(out_w1, out_b1, out);
    }
    k4_mma<<<(V + 255) / 256, 512, K4_SMEM>>>(out_w2, out_b2);
    k5b_final<<<(B * VO + 255) / 256, 256>>>(out);
    k5c_scatter<<<(B * S + 255) / 256, 256>>>(ewo, out);
}

// round 9
// speedup vs baseline: 1.1143x; 1.1143x over previous
#include <cuda_runtime.h>
#include <cuda_fp16.h>
#include <math.h>

#define B 128
#define S 400
#define H 256
#define E 128
#define V 50000
#define OOV 50
#define TWOH 512
#define VO (V + OOV)

#define OFF_HT   (B * VO)
#define OFF_CT   (OFF_HT + B * H)
#define OFF_CTX  (OFF_CT + B * H)
#define OFF_AT   (OFF_CTX + B * TWOH)
#define OFF_GP   (OFF_AT + B * S)
#define OFF_COV  (OFF_GP + B)

__device__ float g_decbase[B * TWOH];
__device__ float g_gpart[B];
__device__ float g_et[B * S];
__device__ float g_hidden[B * H];
__device__ float g_logits[(size_t)B * V];
__device__ float g_psum[B];
__device__ float g_ctxpart[B * 4 * TWOH];
// Wh pre-split fp16 hi, k-pair packed, chunked: [16 chunks][512 n][16 kp]
__device__ unsigned g_WhHi[16 * 512 * 16];

__device__ __forceinline__ float sigf(float x) { return 1.0f / (1.0f + expf(-x)); }

__device__ __forceinline__ float wred(float a) {
    a += __shfl_xor_sync(0xffffffffu, a, 16);
    a += __shfl_xor_sync(0xffffffffu, a, 8);
    a += __shfl_xor_sync(0xffffffffu, a, 4);
    a += __shfl_xor_sync(0xffffffffu, a, 2);
    a += __shfl_xor_sync(0xffffffffu, a, 1);
    return a;
}

__device__ __forceinline__ void splitpack(float x, float y, unsigned& hi, unsigned& lo) {
    __half hx = __float2half_rn(x), hy = __float2half_rn(y);
    __half lx = __float2half_rn(x - __half2float(hx));
    __half ly = __float2half_rn(y - __half2float(hy));
    hi = ((unsigned)__half_as_ushort(hy) << 16) | (unsigned)__half_as_ushort(hx);
    lo = ((unsigned)__half_as_ushort(ly) << 16) | (unsigned)__half_as_ushort(lx);
}

__device__ __forceinline__ void mma16(float c[4], const unsigned a[4], unsigned b0, unsigned b1) {
    asm("mma.sync.aligned.m16n8k16.row.col.f32.f16.f16.f32 "
        "{%0,%1,%2,%3}, {%4,%5,%6,%7}, {%8,%9}, {%0,%1,%2,%3};"
        : "+f"(c[0]), "+f"(c[1]), "+f"(c[2]), "+f"(c[3])
        : "r"(a[0]), "r"(a[1]), "r"(a[2]), "r"(a[3]), "r"(b0), "r"(b1));
}

// ---------------------------------------------------------------------------
// K0: pre-split Wh into fp16 hi, k-pair packed; zero g_psum. grid=(512), 256thr.
// ---------------------------------------------------------------------------
__global__ void k0_wh(const float* __restrict__ Wh)
{
    int idx = blockIdx.x * 256 + threadIdx.x;
    int n = idx >> 8;
    int kpg = idx & 255;
    int k = kpg * 2;
    int c = k >> 5, kp = (k & 31) >> 1;
    float2 v = *(const float2*)(Wh + (size_t)n * TWOH + k);
    unsigned hi, lo;
    splitpack(v.x, v.y, hi, lo);
    g_WhHi[(c * 512 + n) * 16 + kp] = hi;
    if (blockIdx.x == 0 && threadIdx.x < B) g_psum[threadIdx.x] = 0.f;
}

// ---------------------------------------------------------------------------
// K1: embedding + input proj + LSTM + decbase + gen_p partial. grid=(B), 256thr.
// ---------------------------------------------------------------------------
__global__ void k1_lstm(
    const int* __restrict__ idx, const float* __restrict__ h0, const float* __restrict__ c0,
    const float* __restrict__ ctxv, const float* __restrict__ emb,
    const float* __restrict__ Wi, const float* __restrict__ bi,
    const float* __restrict__ W_ih, const float* __restrict__ W_hh,
    const float* __restrict__ b_ih, const float* __restrict__ b_hh,
    const float* __restrict__ att_ws, const float* __restrict__ att_bc,
    const float* __restrict__ gp_ws, const float* __restrict__ gp_bs,
    const float* __restrict__ gp_wx, const float* __restrict__ gp_bx,
    const float* __restrict__ gp_bh,
    float* __restrict__ out)
{
    const int b = blockIdx.x;
    const int tid = threadIdx.x;
    const int w = tid >> 5, lane = tid & 31;

    __shared__ float s_in[TWOH + E];
    __shared__ float s_x[E];
    __shared__ float s_h0[H];
    __shared__ float s_gates[4 * H];
    __shared__ float s_st[TWOH];
    __shared__ float s_red[256];

    for (int k = tid; k < TWOH; k += 256) s_in[k] = ctxv[b * TWOH + k];
    if (tid < E) s_in[TWOH + tid] = emb[(size_t)idx[b] * E + tid];
    s_h0[tid] = h0[b * H + tid];
    __syncthreads();

    for (int o = w * 16; o < (w + 1) * 16; o++) {
        const float* wr = Wi + (size_t)o * (TWOH + E);
        float a = 0.f;
        for (int k = lane; k < TWOH + E; k += 32) a += wr[k] * s_in[k];
        a = wred(a);
        if (lane == 0) s_x[o] = a + bi[o];
    }
    __syncthreads();

    for (int o = w * 128; o < (w + 1) * 128; o++) {
        const float* wi_ = W_ih + (size_t)o * E;
        const float* wh_ = W_hh + (size_t)o * H;
        float a = 0.f;
        for (int k = lane; k < E; k += 32) a += wi_[k] * s_x[k];
        for (int k = lane; k < H; k += 32) a += wh_[k] * s_h0[k];
        a = wred(a);
        if (lane == 0) s_gates[o] = a + b_ih[o] + b_hh[o];
    }
    __syncthreads();

    {
        float ig = sigf(s_gates[tid]);
        float fg = sigf(s_gates[H + tid]);
        float gg = tanhf(s_gates[2 * H + tid]);
        float og = sigf(s_gates[3 * H + tid]);
        float c = fg * c0[b * H + tid] + ig * gg;
        float h = og * tanhf(c);
        out[OFF_HT + b * H + tid] = h;
        out[OFF_CT + b * H + tid] = c;
        s_st[tid] = h;
        s_st[H + tid] = c;
    }
    __syncthreads();

    for (int o = w * 64; o < (w + 1) * 64; o++) {
        const float* wr = att_ws + (size_t)o * TWOH;
        float a = 0.f;
        for (int k = lane; k < TWOH; k += 32) a += wr[k] * s_st[k];
        a = wred(a);
        if (lane == 0) g_decbase[b * TWOH + o] = a + att_bc[o];
    }

    float p = 0.f;
    for (int k = tid; k < TWOH; k += 256) p += gp_ws[k] * s_st[k];
    if (tid < E) p += gp_wx[tid] * s_x[tid];
    s_red[tid] = p;
    __syncthreads();
    for (int off = 128; off > 0; off >>= 1) {
        if (tid < off) s_red[tid] += s_red[tid + off];
        __syncthreads();
    }
    if (tid == 0) g_gpart[b] = s_red[0] + gp_bs[0] + gp_bx[0] + gp_bh[0];
}

// ---------------------------------------------------------------------------
// K2: attention scores, fp16 mma two-product (fp32 acc), double-buffered
// register-prefetch pipeline (R7 version — fastest measured).
// Block: 64 rows x 512 n, K=512 in 16 chunks of 32. 512thr = 16 warps (2m x 8n).
// ---------------------------------------------------------------------------
#define K2P 20
#define K2_BUF 51200
#define K2_AH 0
#define K2_AL 5120
#define K2_BH 10240
#define K2_SV  102400
#define K2_SWC 104448
#define K2_SDB 106496
#define K2_EP  110592
#define K2_SMEM 112640

__global__ void __launch_bounds__(512, 1) k2_mma(
    const float* __restrict__ EO,
    const float* __restrict__ att_wc, const float* __restrict__ att_v,
    const float* __restrict__ coverage, const int* __restrict__ mask)
{
    extern __shared__ char smem[];
    float* sv  = (float*)(smem + K2_SV);
    float* swc = (float*)(smem + K2_SWC);
    float* sdb = (float*)(smem + K2_SDB);
    float* ep  = (float*)(smem + K2_EP);

    const int tid = threadIdx.x;
    const int w = tid >> 5, lane = tid & 31;
    const int g = lane >> 2, t = lane & 3;
    const int wm = w & 1, wn = w >> 1;
    const int row0 = blockIdx.x * 64;
    const int b0 = row0 / S;
    const int b1e = (row0 + 63) / S;

    sv[tid] = att_v[tid];
    swc[tid] = att_wc[tid];
    sdb[tid] = g_decbase[b0 * TWOH + tid];
    sdb[512 + tid] = g_decbase[b1e * TWOH + tid];

    const int ar = tid >> 3, aq = tid & 7;
    const int bn = tid >> 2, bkq = tid & 3;
    const float* aptr = EO + (size_t)(row0 + ar) * TWOH + aq * 4;

    float c[2][8][4];
    #pragma unroll
    for (int mi = 0; mi < 2; mi++)
        #pragma unroll
        for (int ni = 0; ni < 8; ni++)
            #pragma unroll
            for (int q = 0; q < 4; q++) c[mi][ni][q] = 0.f;

    float4 av;
    uint4 bv[4];

    // prologue: chunk 0 loads
    av = *(const float4*)(aptr);
    #pragma unroll
    for (int i = 0; i < 4; i++)
        bv[i] = *(const uint4*)(g_WhHi + ((size_t)(i * 128 + bn) * 16 + bkq * 4));
    {
        unsigned h0_, l0_, h1_, l1_;
        splitpack(av.x, av.y, h0_, l0_);
        splitpack(av.z, av.w, h1_, l1_);
        *(uint2*)((unsigned*)(smem + K2_AH) + ar * K2P + aq * 2) = make_uint2(h0_, h1_);
        *(uint2*)((unsigned*)(smem + K2_AL) + ar * K2P + aq * 2) = make_uint2(l0_, l1_);
        unsigned* BHp = (unsigned*)(smem + K2_BH);
        #pragma unroll
        for (int i = 0; i < 4; i++)
            *(uint4*)(BHp + (i * 128 + bn) * K2P + bkq * 4) = bv[i];
    }
    __syncthreads();

    for (int kt = 0; kt < 16; kt++) {
        char* bufc = smem + (kt & 1) * K2_BUF;
        if (kt < 15) {
            av = *(const float4*)(aptr + (kt + 1) * 32);
            #pragma unroll
            for (int i = 0; i < 4; i++)
                bv[i] = *(const uint4*)(g_WhHi + ((size_t)((kt + 1) * 512 + i * 128 + bn) * 16 + bkq * 4));
        }

        unsigned* AHc = (unsigned*)(bufc + K2_AH);
        unsigned* ALc = (unsigned*)(bufc + K2_AL);
        unsigned* BHc = (unsigned*)(bufc + K2_BH);
        #pragma unroll
        for (int s = 0; s < 2; s++) {
            unsigned ah[2][4], al[2][4];
            #pragma unroll
            for (int mi = 0; mi < 2; mi++) {
                const unsigned* pa = AHc + (wm * 32 + mi * 16 + g) * K2P + s * 8 + t;
                ah[mi][0] = pa[0]; ah[mi][1] = pa[8 * K2P];
                ah[mi][2] = pa[4]; ah[mi][3] = pa[8 * K2P + 4];
                const unsigned* pl = ALc + (wm * 32 + mi * 16 + g) * K2P + s * 8 + t;
                al[mi][0] = pl[0]; al[mi][1] = pl[8 * K2P];
                al[mi][2] = pl[4]; al[mi][3] = pl[8 * K2P + 4];
            }
            #pragma unroll
            for (int ni = 0; ni < 8; ni++) {
                const unsigned* pb = BHc + (wn * 64 + ni * 8 + g) * K2P + s * 8 + t;
                unsigned bh0 = pb[0], bh1 = pb[4];
                #pragma unroll
                for (int mi = 0; mi < 2; mi++) {
                    mma16(c[mi][ni], ah[mi], bh0, bh1);
                    mma16(c[mi][ni], al[mi], bh0, bh1);
                }
            }
        }

        if (kt < 15) {
            char* bufn = smem + ((kt + 1) & 1) * K2_BUF;
            unsigned h0_, l0_, h1_, l1_;
            splitpack(av.x, av.y, h0_, l0_);
            splitpack(av.z, av.w, h1_, l1_);
            *(uint2*)((unsigned*)(bufn + K2_AH) + ar * K2P + aq * 2) = make_uint2(h0_, h1_);
            *(uint2*)((unsigned*)(bufn + K2_AL) + ar * K2P + aq * 2) = make_uint2(l0_, l1_);
            unsigned* BHn = (unsigned*)(bufn + K2_BH);
            #pragma unroll
            for (int i = 0; i < 4; i++)
                *(uint4*)(BHn + (i * 128 + bn) * K2P + bkq * 4) = bv[i];
        }
        __syncthreads();
    }

    // epilogue: exact tanh + v-dot; reduce over tg, then over 8 n-warps
    #pragma unroll
    for (int mi = 0; mi < 2; mi++) {
        #pragma unroll
        for (int hf = 0; hf < 2; hf++) {
            const int rl = wm * 32 + mi * 16 + hf * 8 + g;
            const int r = row0 + rl;
            const int dbo = (r / S != b0) ? 512 : 0;
            const float cov = coverage[r];
            float acc = 0.f;
            #pragma unroll
            for (int ni = 0; ni < 8; ni++) {
                const int j = wn * 64 + ni * 8 + t * 2;
                float v0 = c[mi][ni][hf * 2 + 0] + sdb[dbo + j] + cov * swc[j];
                float v1 = c[mi][ni][hf * 2 + 1] + sdb[dbo + j + 1] + cov * swc[j + 1];
                acc += sv[j] * tanhf(v0) + sv[j + 1] * tanhf(v1);
            }
            acc += __shfl_xor_sync(0xffffffffu, acc, 1);
            acc += __shfl_xor_sync(0xffffffffu, acc, 2);
            if (t == 0) ep[rl * 8 + wn] = acc;
        }
    }
    __syncthreads();
    if (tid < 64) {
        float sacc = 0.f;
        #pragma unroll
        for (int q = 0; q < 8; q++) sacc += ep[tid * 8 + q];
        const int r = row0 + tid;
        g_et[r] = (mask[r] == 0) ? -1e30f : sacc;
    }
}

// ---------------------------------------------------------------------------
// K3a: masked softmax over S -> a_t, next_coverage. grid=(B), 512thr.
// ---------------------------------------------------------------------------
__global__ void k3a_softmax(const float* __restrict__ coverage, float* __restrict__ out)
{
    const int b = blockIdx.x;
    const int t = threadIdx.x;
    __shared__ float red[512];

    float e = (t < S) ? g_et[b * S + t] : -1e30f;
    red[t] = e;
    __syncthreads();
    for (int off = 256; off > 0; off >>= 1) {
        if (t < off) red[t] = fmaxf(red[t], red[t + off]);
        __syncthreads();
    }
    const float mx = red[0];
    __syncthreads();

    float ex = (t < S) ? expf(e - mx) : 0.f;
    red[t] = ex;
    __syncthreads();
    for (int off = 256; off > 0; off >>= 1) {
        if (t < off) red[t] += red[t + off];
        __syncthreads();
    }
    const float inv = 1.f / red[0];

    if (t < S) {
        float a = ex * inv;
        out[OFF_AT + b * S + t] = a;
        out[OFF_COV + b * S + t] = coverage[b * S + t] + a;
    }
}

// ---------------------------------------------------------------------------
// K3c: ctx partials. grid=(B*4), 512thr.
// ---------------------------------------------------------------------------
__global__ void k3c_ctxpart(const float* __restrict__ EO, const float* __restrict__ out)
{
    const int blk = blockIdx.x;
    const int b = blk >> 2, q = blk & 3;
    const int t = threadIdx.x;
    __shared__ float sa[100];
    if (t < 100) sa[t] = out[OFF_AT + b * S + q * 100 + t];
    __syncthreads();
    const float* eob = EO + ((size_t)b * S + q * 100) * TWOH;
    float c = 0.f;
    #pragma unroll 10
    for (int s = 0; s < 100; s++) c += sa[s] * eob[(size_t)s * TWOH + t];
    g_ctxpart[(size_t)blk * TWOH + t] = c;
}

// ---------------------------------------------------------------------------
// K3d: combine ctx partials + gen_p. grid=(B), 512thr.
// ---------------------------------------------------------------------------
__global__ void k3d_ctx(const float* __restrict__ gp_wh, float* __restrict__ out)
{
    const int b = blockIdx.x;
    const int t = threadIdx.x;
    __shared__ float red[512];
    float c = g_ctxpart[(size_t)(b * 4 + 0) * TWOH + t]
            + g_ctxpart[(size_t)(b * 4 + 1) * TWOH + t]
            + g_ctxpart[(size_t)(b * 4 + 2) * TWOH + t]
            + g_ctxpart[(size_t)(b * 4 + 3) * TWOH + t];
    out[OFF_CTX + b * TWOH + t] = c;
    red[t] = gp_wh[t] * c;
    __syncthreads();
    for (int off = 256; off > 0; off >>= 1) {
        if (t < off) red[t] += red[t + off];
        __syncthreads();
    }
    if (t == 0) out[OFF_GP + b] = sigf(red[0] + g_gpart[b]);
}

// ---------------------------------------------------------------------------
// K3b: hidden = relu(out_w1 @ [h_t, ctx] + b1), tiled 64x64. grid=(4,2), 256thr.
// ---------------------------------------------------------------------------
__global__ void k3b_hidden(
    const float* __restrict__ out_w1, const float* __restrict__ out_b1,
    const float* __restrict__ out)
{
    __shared__ __align__(16) float As[16][68];
    __shared__ __align__(16) float Ws[16][68];

    const int tid = threadIdx.x;
    const int tx = tid & 15, ty = tid >> 4;
    const int rl = tid >> 2, kq = tid & 3;
    const int m0 = blockIdx.y * 64;
    const int n0 = blockIdx.x * 64;

    float acc[4][4];
    #pragma unroll
    for (int a = 0; a < 4; a++)
        #pragma unroll
        for (int c = 0; c < 4; c++) acc[a][c] = 0.f;

    for (int kt = 0; kt < 48; kt++) {
        const int k = kt * 16 + kq * 4;
        const int m = m0 + rl;
        float4 av = (k < H)
            ? *(const float4*)(out + OFF_HT + m * H + k)
            : *(const float4*)(out + OFF_CTX + m * TWOH + (k - H));
        float4 wv = *(const float4*)(out_w1 + (size_t)(n0 + rl) * (H + TWOH) + k);
        __syncthreads();
        As[kq * 4 + 0][rl] = av.x; As[kq * 4 + 1][rl] = av.y;
        As[kq * 4 + 2][rl] = av.z; As[kq * 4 + 3][rl] = av.w;
        Ws[kq * 4 + 0][rl] = wv.x; Ws[kq * 4 + 1][rl] = wv.y;
        Ws[kq * 4 + 2][rl] = wv.z; Ws[kq * 4 + 3][rl] = wv.w;
        __syncthreads();
        #pragma unroll
        for (int kk = 0; kk < 16; kk++) {
            float ar[4], wr[4];
            *(float4*)ar = *(const float4*)&As[kk][ty * 4];
            *(float4*)wr = *(const float4*)&Ws[kk][tx * 4];
            #pragma unroll
            for (int mi = 0; mi < 4; mi++)
                #pragma unroll
                for (int jj = 0; jj < 4; jj++)
                    acc[mi][jj] += ar[mi] * wr[jj];
        }
    }

    #pragma unroll
    for (int mi = 0; mi < 4; mi++) {
        const int m = m0 + ty * 4 + mi;
        #pragma unroll
        for (int jj = 0; jj < 4; jj++) {
            const int o = n0 + tx * 4 + jj;
            g_hidden[m * H + o] = fmaxf(acc[mi][jj] + out_b1[o], 0.f);
        }
    }
}

// ---------------------------------------------------------------------------
// K4: logits GEMM + fused vocab sum-exp (no max shift; logits are O(1)).
// fp16 two-product, double-buffered register-prefetch. 128m x 256n, 512thr.
// ---------------------------------------------------------------------------
#define K4_BUF 40960
#define K4_AH 0
#define K4_AL 10240
#define K4_BH 20480
#define K4_SMEM 81920

__global__ void __launch_bounds__(512, 1) k4_mma(
    const float* __restrict__ W2, const float* __restrict__ b2)
{
    extern __shared__ char smem[];

    const int tid = threadIdx.x;
    const int w = tid >> 5, lane = tid & 31;
    const int g = lane >> 2, t = lane & 3;
    const int wm = w & 3, wn = w >> 2;
    const int j0 = blockIdx.x * 256;

    const int ar = tid >> 3, aq = tid & 7;
    const int br = tid >> 3, bq = tid & 7;

    float c[2][8][4];
    #pragma unroll
    for (int mi = 0; mi < 2; mi++)
        #pragma unroll
        for (int ni = 0; ni < 8; ni++)
            #pragma unroll
            for (int q = 0; q < 4; q++) c[mi][ni][q] = 0.f;

    float4 avv[2], bvv[4];

    #pragma unroll
    for (int i = 0; i < 2; i++)
        avv[i] = *(const float4*)(g_hidden + (size_t)(i * 64 + ar) * H + aq * 4);
    #pragma unroll
    for (int i = 0; i < 4; i++) {
        int j = j0 + i * 64 + br;
        bvv[i] = (j < V) ? *(const float4*)(W2 + (size_t)j * H + bq * 4)
                         : make_float4(0.f, 0.f, 0.f, 0.f);
    }
    {
        unsigned* AHp = (unsigned*)(smem + K4_AH);
        unsigned* ALp = (unsigned*)(smem + K4_AL);
        unsigned* BHp = (unsigned*)(smem + K4_BH);
        #pragma unroll
        for (int i = 0; i < 2; i++) {
            unsigned h0_, l0_, h1_, l1_;
            splitpack(avv[i].x, avv[i].y, h0_, l0_);
            splitpack(avv[i].z, avv[i].w, h1_, l1_);
            *(uint2*)(AHp + (i * 64 + ar) * K2P + aq * 2) = make_uint2(h0_, h1_);
            *(uint2*)(ALp + (i * 64 + ar) * K2P + aq * 2) = make_uint2(l0_, l1_);
        }
        #pragma unroll
        for (int i = 0; i < 4; i++) {
            unsigned h0_, l0_, h1_, l1_;
            splitpack(bvv[i].x, bvv[i].y, h0_, l0_);
            splitpack(bvv[i].z, bvv[i].w, h1_, l1_);
            *(uint2*)(BHp + (i * 64 + br) * K2P + bq * 2) = make_uint2(h0_, h1_);
        }
    }
    __syncthreads();

    for (int kt = 0; kt < 8; kt++) {
        char* bufc = smem + (kt & 1) * K4_BUF;
        if (kt < 7) {
            const int k0 = (kt + 1) * 32;
            #pragma unroll
            for (int i = 0; i < 2; i++)
                avv[i] = *(const float4*)(g_hidden + (size_t)(i * 64 + ar) * H + k0 + aq * 4);
            #pragma unroll
            for (int i = 0; i < 4; i++) {
                int j = j0 + i * 64 + br;
                bvv[i] = (j < V) ? *(const float4*)(W2 + (size_t)j * H + k0 + bq * 4)
                                 : make_float4(0.f, 0.f, 0.f, 0.f);
            }
        }

        unsigned* AHc = (unsigned*)(bufc + K4_AH);
        unsigned* ALc = (unsigned*)(bufc + K4_AL);
        unsigned* BHc = (unsigned*)(bufc + K4_BH);
        #pragma unroll
        for (int s = 0; s < 2; s++) {
            unsigned ah[2][4], al[2][4];
            #pragma unroll
            for (int mi = 0; mi < 2; mi++) {
                const unsigned* pa = AHc + (wm * 32 + mi * 16 + g) * K2P + s * 8 + t;
                ah[mi][0] = pa[0]; ah[mi][1] = pa[8 * K2P];
                ah[mi][2] = pa[4]; ah[mi][3] = pa[8 * K2P + 4];
                const unsigned* pl = ALc + (wm * 32 + mi * 16 + g) * K2P + s * 8 + t;
                al[mi][0] = pl[0]; al[mi][1] = pl[8 * K2P];
                al[mi][2] = pl[4]; al[mi][3] = pl[8 * K2P + 4];
            }
            #pragma unroll
            for (int ni = 0; ni < 8; ni++) {
                const unsigned* pb = BHc + (wn * 64 + ni * 8 + g) * K2P + s * 8 + t;
                unsigned bh0 = pb[0], bh1 = pb[4];
                #pragma unroll
                for (int mi = 0; mi < 2; mi++) {
                    mma16(c[mi][ni], ah[mi], bh0, bh1);
                    mma16(c[mi][ni], al[mi], bh0, bh1);
                }
            }
        }

        if (kt < 7) {
            char* bufn = smem + ((kt + 1) & 1) * K4_BUF;
            unsigned* AHn = (unsigned*)(bufn + K4_AH);
            unsigned* ALn = (unsigned*)(bufn + K4_AL);
            unsigned* BHn = (unsigned*)(bufn + K4_BH);
            #pragma unroll
            for (int i = 0; i < 2; i++) {
                unsigned h0_, l0_, h1_, l1_;
                splitpack(avv[i].x, avv[i].y, h0_, l0_);
                splitpack(avv[i].z, avv[i].w, h1_, l1_);
                *(uint2*)(AHn + (i * 64 + ar) * K2P + aq * 2) = make_uint2(h0_, h1_);
                *(uint2*)(ALn + (i * 64 + ar) * K2P + aq * 2) = make_uint2(l0_, l1_);
            }
            #pragma unroll
            for (int i = 0; i < 4; i++) {
                unsigned h0_, l0_, h1_, l1_;
                splitpack(bvv[i].x, bvv[i].y, h0_, l0_);
                splitpack(bvv[i].z, bvv[i].w, h1_, l1_);
                *(uint2*)(BHn + (i * 64 + br) * K2P + bq * 2) = make_uint2(h0_, h1_);
            }
        }
        __syncthreads();
    }

    // epilogue: write logits + per-row partial sum of exp(logit)
    float* ssum = (float*)smem;
    #pragma unroll
    for (int mi = 0; mi < 2; mi++) {
        #pragma unroll
        for (int hf = 0; hf < 2; hf++) {
            const int r = wm * 32 + mi * 16 + hf * 8 + g;
            float ps = 0.f;
            #pragma unroll
            for (int ni = 0; ni < 8; ni++) {
                const int j = j0 + wn * 64 + ni * 8 + t * 2;
                if (j < V) {
                    float o0 = c[mi][ni][hf * 2 + 0] + b2[j];
                    float o1 = c[mi][ni][hf * 2 + 1] + b2[j + 1];
                    *(float2*)(g_logits + (size_t)r * V + j) = make_float2(o0, o1);
                    ps += expf(o0) + expf(o1);
                }
            }
            ps += __shfl_xor_sync(0xffffffffu, ps, 1);
            ps += __shfl_xor_sync(0xffffffffu, ps, 2);
            if (t == 0) ssum[r * 4 + wn] = ps;
        }
    }
    __syncthreads();
    if (tid < 128) {
        float s2 = ssum[tid * 4] + ssum[tid * 4 + 1] + ssum[tid * 4 + 2] + ssum[tid * 4 + 3];
        atomicAdd(&g_psum[tid], s2);
    }
}

// ---------------------------------------------------------------------------
// K5b: final_dist = exp(logit)/sumexp * gen_p, zero OOV tail.
// ---------------------------------------------------------------------------
__global__ void k5b_final(float* __restrict__ out)
{
    const int i = blockIdx.x * 256 + threadIdx.x;
    if (i >= B * VO) return;
    const int b = i / VO;
    const int c = i - b * VO;
    float v = 0.f;
    if (c < V) {
        const float gp = out[OFF_GP + b];
        v = expf(g_logits[(size_t)b * V + c]) * (1.f / g_psum[b]) * gp;
    }
    out[i] = v;
}

__global__ void k5c_scatter(const int* __restrict__ ewo, float* __restrict__ out)
{
    const int i = blockIdx.x * 256 + threadIdx.x;
    if (i >= B * S) return;
    const int b = i / S;
    const float gp = out[OFF_GP + b];
    const float a = out[OFF_AT + i];
    atomicAdd(out + (size_t)b * VO + ewo[i], a * (1.f - gp));
}

// ---------------------------------------------------------------------------
extern "C" void kernel_launch(void* const* d_in, const int* in_sizes, int n_in,
                              void* d_out, int out_size)
{
    const int*   idx      = (const int*)  d_in[0];
    const float* h0       = (const float*)d_in[1];
    const float* c0       = (const float*)d_in[2];
    const float* EO       = (const float*)d_in[3];
    const int*   emask    = (const int*)  d_in[4];
    const float* ctxv     = (const float*)d_in[5];
    const int*   ewo      = (const int*)  d_in[7];
    const float* coverage = (const float*)d_in[8];
    const float* emb      = (const float*)d_in[9];
    const float* Wi       = (const float*)d_in[10];
    const float* bi       = (const float*)d_in[11];
    const float* W_ih     = (const float*)d_in[12];
    const float* W_hh     = (const float*)d_in[13];
    const float* b_ih     = (const float*)d_in[14];
    const float* b_hh     = (const float*)d_in[15];
    const float* att_wh   = (const float*)d_in[16];
    const float* att_ws   = (const float*)d_in[17];
    const float* att_wc   = (const float*)d_in[18];
    const float* att_bc   = (const float*)d_in[19];
    const float* att_v    = (const float*)d_in[20];
    const float* gp_wh    = (const float*)d_in[21];
    const float* gp_bh    = (const float*)d_in[22];
    const float* gp_ws    = (const float*)d_in[23];
    const float* gp_bs    = (const float*)d_in[24];
    const float* gp_wx    = (const float*)d_in[25];
    const float* gp_bx    = (const float*)d_in[26];
    const float* out_w1   = (const float*)d_in[27];
    const float* out_b1   = (const float*)d_in[28];
    const float* out_w2   = (const float*)d_in[29];
    const float* out_b2   = (const float*)d_in[30];
    float* out = (float*)d_out;

    static int attr_done = 0;
    if (!attr_done) {
        cudaFuncSetAttribute(k2_mma, cudaFuncAttributeMaxDynamicSharedMemorySize, K2_SMEM);
        cudaFuncSetAttribute(k4_mma, cudaFuncAttributeMaxDynamicSharedMemorySize, K4_SMEM);
        attr_done = 1;
    }

    k0_wh<<<512, 256>>>(att_wh);
    k1_lstm<<<B, 256>>>(idx, h0, c0, ctxv, emb, Wi, bi, W_ih, W_hh, b_ih, b_hh,
                        att_ws, att_bc, gp_ws, gp_bs, gp_wx, gp_bx, gp_bh, out);
    k2_mma<<<(B * S) / 64, 512, K2_SMEM>>>(EO, att_wc, att_v, coverage, emask);
    k3a_softmax<<<B, 512>>>(coverage, out);
    k3c_ctxpart<<<B * 4, 512>>>(EO, out);
    k3d_ctx<<<B, 512>>>(gp_wh, out);
    {
        dim3 g3b(4, 2);
        k3b_hidden<<<g3b, 256>>>(out_w1, out_b1, out);
    }
    k4_mma<<<(V + 255) / 256, 512, K4_SMEM>>>(out_w2, out_b2);
    k5b_final<<<(B * VO + 255) / 256, 256>>>(out);
    k5c_scatter<<<(B * S + 255) / 256, 256>>>(ewo, out);
}

// round 10
// speedup vs baseline: 1.2799x; 1.1487x over previous
#include <cuda_runtime.h>
#include <cuda_fp16.h>
#include <math.h>

#define B 128
#define S 400
#define H 256
#define E 128
#define V 50000
#define OOV 50
#define TWOH 512
#define VO (V + OOV)

#define OFF_HT   (B * VO)
#define OFF_CT   (OFF_HT + B * H)
#define OFF_CTX  (OFF_CT + B * H)
#define OFF_AT   (OFF_CTX + B * TWOH)
#define OFF_GP   (OFF_AT + B * S)
#define OFF_COV  (OFF_GP + B)

__device__ float g_decbase[B * TWOH];
__device__ float g_gpart[B];
__device__ float g_et[B * S];
__device__ float g_hidden[B * H];
__device__ float g_logits[(size_t)B * V];   // holds exp(logit) after k4
__device__ float g_psum[B];
__device__ float g_ctxpart[B * 4 * TWOH];
// Wh pre-packed fp16 hi, k-pair packed, chunked: [16 chunks][512 n][16 kp]
__device__ unsigned g_WhHi[16 * 512 * 16];

__device__ __forceinline__ float sigf(float x) { return 1.0f / (1.0f + expf(-x)); }

__device__ __forceinline__ float wred(float a) {
    a += __shfl_xor_sync(0xffffffffu, a, 16);
    a += __shfl_xor_sync(0xffffffffu, a, 8);
    a += __shfl_xor_sync(0xffffffffu, a, 4);
    a += __shfl_xor_sync(0xffffffffu, a, 2);
    a += __shfl_xor_sync(0xffffffffu, a, 1);
    return a;
}

__device__ __forceinline__ unsigned packhi(float x, float y) {
    __half hx = __float2half_rn(x), hy = __float2half_rn(y);
    return ((unsigned)__half_as_ushort(hy) << 16) | (unsigned)__half_as_ushort(hx);
}

__device__ __forceinline__ void splitpack(float x, float y, unsigned& hi, unsigned& lo) {
    __half hx = __float2half_rn(x), hy = __float2half_rn(y);
    __half lx = __float2half_rn(x - __half2float(hx));
    __half ly = __float2half_rn(y - __half2float(hy));
    hi = ((unsigned)__half_as_ushort(hy) << 16) | (unsigned)__half_as_ushort(hx);
    lo = ((unsigned)__half_as_ushort(ly) << 16) | (unsigned)__half_as_ushort(lx);
}

__device__ __forceinline__ void mma16(float c[4], const unsigned a[4], unsigned b0, unsigned b1) {
    asm("mma.sync.aligned.m16n8k16.row.col.f32.f16.f16.f32 "
        "{%0,%1,%2,%3}, {%4,%5,%6,%7}, {%8,%9}, {%0,%1,%2,%3};"
        : "+f"(c[0]), "+f"(c[1]), "+f"(c[2]), "+f"(c[3])
        : "r"(a[0]), "r"(a[1]), "r"(a[2]), "r"(a[3]), "r"(b0), "r"(b1));
}

// ---------------------------------------------------------------------------
// K0: pre-pack Wh fp16 hi, k-pair packed; zero g_psum. grid=(512), 256thr.
// ---------------------------------------------------------------------------
__global__ void k0_wh(const float* __restrict__ Wh)
{
    int idx = blockIdx.x * 256 + threadIdx.x;
    int n = idx >> 8;
    int kpg = idx & 255;
    int k = kpg * 2;
    int c = k >> 5, kp = (k & 31) >> 1;
    float2 v = *(const float2*)(Wh + (size_t)n * TWOH + k);
    g_WhHi[(c * 512 + n) * 16 + kp] = packhi(v.x, v.y);
    if (blockIdx.x == 0 && threadIdx.x < B) g_psum[threadIdx.x] = 0.f;
}

// ---------------------------------------------------------------------------
// K1: embedding + input proj + LSTM + decbase + gen_p partial. grid=(B), 256thr.
// ---------------------------------------------------------------------------
__global__ void k1_lstm(
    const int* __restrict__ idx, const float* __restrict__ h0, const float* __restrict__ c0,
    const float* __restrict__ ctxv, const float* __restrict__ emb,
    const float* __restrict__ Wi, const float* __restrict__ bi,
    const float* __restrict__ W_ih, const float* __restrict__ W_hh,
    const float* __restrict__ b_ih, const float* __restrict__ b_hh,
    const float* __restrict__ att_ws, const float* __restrict__ att_bc,
    const float* __restrict__ gp_ws, const float* __restrict__ gp_bs,
    const float* __restrict__ gp_wx, const float* __restrict__ gp_bx,
    const float* __restrict__ gp_bh,
    float* __restrict__ out)
{
    const int b = blockIdx.x;
    const int tid = threadIdx.x;
    const int w = tid >> 5, lane = tid & 31;

    __shared__ float s_in[TWOH + E];
    __shared__ float s_x[E];
    __shared__ float s_h0[H];
    __shared__ float s_gates[4 * H];
    __shared__ float s_st[TWOH];
    __shared__ float s_red[256];

    for (int k = tid; k < TWOH; k += 256) s_in[k] = ctxv[b * TWOH + k];
    if (tid < E) s_in[TWOH + tid] = emb[(size_t)idx[b] * E + tid];
    s_h0[tid] = h0[b * H + tid];
    __syncthreads();

    for (int o = w * 16; o < (w + 1) * 16; o++) {
        const float* wr = Wi + (size_t)o * (TWOH + E);
        float a = 0.f;
        for (int k = lane; k < TWOH + E; k += 32) a += wr[k] * s_in[k];
        a = wred(a);
        if (lane == 0) s_x[o] = a + bi[o];
    }
    __syncthreads();

    for (int o = w * 128; o < (w + 1) * 128; o++) {
        const float* wi_ = W_ih + (size_t)o * E;
        const float* wh_ = W_hh + (size_t)o * H;
        float a = 0.f;
        for (int k = lane; k < E; k += 32) a += wi_[k] * s_x[k];
        for (int k = lane; k < H; k += 32) a += wh_[k] * s_h0[k];
        a = wred(a);
        if (lane == 0) s_gates[o] = a + b_ih[o] + b_hh[o];
    }
    __syncthreads();

    {
        float ig = sigf(s_gates[tid]);
        float fg = sigf(s_gates[H + tid]);
        float gg = tanhf(s_gates[2 * H + tid]);
        float og = sigf(s_gates[3 * H + tid]);
        float c = fg * c0[b * H + tid] + ig * gg;
        float h = og * tanhf(c);
        out[OFF_HT + b * H + tid] = h;
        out[OFF_CT + b * H + tid] = c;
        s_st[tid] = h;
        s_st[H + tid] = c;
    }
    __syncthreads();

    for (int o = w * 64; o < (w + 1) * 64; o++) {
        const float* wr = att_ws + (size_t)o * TWOH;
        float a = 0.f;
        for (int k = lane; k < TWOH; k += 32) a += wr[k] * s_st[k];
        a = wred(a);
        if (lane == 0) g_decbase[b * TWOH + o] = a + att_bc[o];
    }

    float p = 0.f;
    for (int k = tid; k < TWOH; k += 256) p += gp_ws[k] * s_st[k];
    if (tid < E) p += gp_wx[tid] * s_x[tid];
    s_red[tid] = p;
    __syncthreads();
    for (int off = 128; off > 0; off >>= 1) {
        if (tid < off) s_red[tid] += s_red[tid + off];
        __syncthreads();
    }
    if (tid == 0) g_gpart[b] = s_red[0] + gp_bs[0] + gp_bx[0] + gp_bh[0];
}

// ---------------------------------------------------------------------------
// K2: attention scores, SINGLE-product fp16 mma (fp32 acc), double-buffered
// register-prefetch pipeline.
// Block: 64 rows x 512 n, K=512 in 16 chunks of 32. 512thr = 16 warps (2m x 8n).
// Per buffer: AH [64][20]u32 (5120B) | BH [512][20]u32 (40960B).
// ---------------------------------------------------------------------------
#define K2P 20
#define K2_AH 0
#define K2_BH 5120
#define K2_BUF 46080
#define K2_SV  92160
#define K2_SWC 94208
#define K2_SDB 96256
#define K2_EP  100352
#define K2_SMEM 102400

__global__ void __launch_bounds__(512, 1) k2_mma(
    const float* __restrict__ EO,
    const float* __restrict__ att_wc, const float* __restrict__ att_v,
    const float* __restrict__ coverage, const int* __restrict__ mask)
{
    extern __shared__ char smem[];
    float* sv  = (float*)(smem + K2_SV);
    float* swc = (float*)(smem + K2_SWC);
    float* sdb = (float*)(smem + K2_SDB);
    float* ep  = (float*)(smem + K2_EP);

    const int tid = threadIdx.x;
    const int w = tid >> 5, lane = tid & 31;
    const int g = lane >> 2, t = lane & 3;
    const int wm = w & 1, wn = w >> 1;
    const int row0 = blockIdx.x * 64;
    const int b0 = row0 / S;
    const int b1e = (row0 + 63) / S;

    sv[tid] = att_v[tid];
    swc[tid] = att_wc[tid];
    sdb[tid] = g_decbase[b0 * TWOH + tid];
    sdb[512 + tid] = g_decbase[b1e * TWOH + tid];

    const int ar = tid >> 3, aq = tid & 7;
    const int bn = tid >> 2, bkq = tid & 3;
    const float* aptr = EO + (size_t)(row0 + ar) * TWOH + aq * 4;

    float c[2][8][4];
    #pragma unroll
    for (int mi = 0; mi < 2; mi++)
        #pragma unroll
        for (int ni = 0; ni < 8; ni++)
            #pragma unroll
            for (int q = 0; q < 4; q++) c[mi][ni][q] = 0.f;

    float4 av;
    uint4 bv[4];

    // prologue: chunk 0 loads
    av = *(const float4*)(aptr);
    #pragma unroll
    for (int i = 0; i < 4; i++)
        bv[i] = *(const uint4*)(g_WhHi + ((size_t)(i * 128 + bn) * 16 + bkq * 4));
    {
        *(uint2*)((unsigned*)(smem + K2_AH) + ar * K2P + aq * 2) =
            make_uint2(packhi(av.x, av.y), packhi(av.z, av.w));
        unsigned* BHp = (unsigned*)(smem + K2_BH);
        #pragma unroll
        for (int i = 0; i < 4; i++)
            *(uint4*)(BHp + (i * 128 + bn) * K2P + bkq * 4) = bv[i];
    }
    __syncthreads();

    for (int kt = 0; kt < 16; kt++) {
        char* bufc = smem + (kt & 1) * K2_BUF;
        if (kt < 15) {
            av = *(const float4*)(aptr + (kt + 1) * 32);
            #pragma unroll
            for (int i = 0; i < 4; i++)
                bv[i] = *(const uint4*)(g_WhHi + ((size_t)((kt + 1) * 512 + i * 128 + bn) * 16 + bkq * 4));
        }

        unsigned* AHc = (unsigned*)(bufc + K2_AH);
        unsigned* BHc = (unsigned*)(bufc + K2_BH);
        #pragma unroll
        for (int s = 0; s < 2; s++) {
            unsigned ah[2][4];
            #pragma unroll
            for (int mi = 0; mi < 2; mi++) {
                const unsigned* pa = AHc + (wm * 32 + mi * 16 + g) * K2P + s * 8 + t;
                ah[mi][0] = pa[0]; ah[mi][1] = pa[8 * K2P];
                ah[mi][2] = pa[4]; ah[mi][3] = pa[8 * K2P + 4];
            }
            #pragma unroll
            for (int ni = 0; ni < 8; ni++) {
                const unsigned* pb = BHc + (wn * 64 + ni * 8 + g) * K2P + s * 8 + t;
                unsigned bh0 = pb[0], bh1 = pb[4];
                #pragma unroll
                for (int mi = 0; mi < 2; mi++)
                    mma16(c[mi][ni], ah[mi], bh0, bh1);
            }
        }

        if (kt < 15) {
            char* bufn = smem + ((kt + 1) & 1) * K2_BUF;
            *(uint2*)((unsigned*)(bufn + K2_AH) + ar * K2P + aq * 2) =
                make_uint2(packhi(av.x, av.y), packhi(av.z, av.w));
            unsigned* BHn = (unsigned*)(bufn + K2_BH);
            #pragma unroll
            for (int i = 0; i < 4; i++)
                *(uint4*)(BHn + (i * 128 + bn) * K2P + bkq * 4) = bv[i];
        }
        __syncthreads();
    }

    // epilogue: exact tanh + v-dot; reduce over tg, then over 8 n-warps
    #pragma unroll
    for (int mi = 0; mi < 2; mi++) {
        #pragma unroll
        for (int hf = 0; hf < 2; hf++) {
            const int rl = wm * 32 + mi * 16 + hf * 8 + g;
            const int r = row0 + rl;
            const int dbo = (r / S != b0) ? 512 : 0;
            const float cov = coverage[r];
            float acc = 0.f;
            #pragma unroll
            for (int ni = 0; ni < 8; ni++) {
                const int j = wn * 64 + ni * 8 + t * 2;
                float v0 = c[mi][ni][hf * 2 + 0] + sdb[dbo + j] + cov * swc[j];
                float v1 = c[mi][ni][hf * 2 + 1] + sdb[dbo + j + 1] + cov * swc[j + 1];
                acc += sv[j] * tanhf(v0) + sv[j + 1] * tanhf(v1);
            }
            acc += __shfl_xor_sync(0xffffffffu, acc, 1);
            acc += __shfl_xor_sync(0xffffffffu, acc, 2);
            if (t == 0) ep[rl * 8 + wn] = acc;
        }
    }
    __syncthreads();
    if (tid < 64) {
        float sacc = 0.f;
        #pragma unroll
        for (int q = 0; q < 8; q++) sacc += ep[tid * 8 + q];
        const int r = row0 + tid;
        g_et[r] = (mask[r] == 0) ? -1e30f : sacc;
    }
}

// ---------------------------------------------------------------------------
// K3a: masked softmax over S -> a_t, next_coverage. grid=(B), 512thr.
// ---------------------------------------------------------------------------
__global__ void k3a_softmax(const float* __restrict__ coverage, float* __restrict__ out)
{
    const int b = blockIdx.x;
    const int t = threadIdx.x;
    __shared__ float red[512];

    float e = (t < S) ? g_et[b * S + t] : -1e30f;
    red[t] = e;
    __syncthreads();
    for (int off = 256; off > 0; off >>= 1) {
        if (t < off) red[t] = fmaxf(red[t], red[t + off]);
        __syncthreads();
    }
    const float mx = red[0];
    __syncthreads();

    float ex = (t < S) ? expf(e - mx) : 0.f;
    red[t] = ex;
    __syncthreads();
    for (int off = 256; off > 0; off >>= 1) {
        if (t < off) red[t] += red[t + off];
        __syncthreads();
    }
    const float inv = 1.f / red[0];

    if (t < S) {
        float a = ex * inv;
        out[OFF_AT + b * S + t] = a;
        out[OFF_COV + b * S + t] = coverage[b * S + t] + a;
    }
}

// ---------------------------------------------------------------------------
// K3c: ctx partials. grid=(B*4), 512thr.
// ---------------------------------------------------------------------------
__global__ void k3c_ctxpart(const float* __restrict__ EO, const float* __restrict__ out)
{
    const int blk = blockIdx.x;
    const int b = blk >> 2, q = blk & 3;
    const int t = threadIdx.x;
    __shared__ float sa[100];
    if (t < 100) sa[t] = out[OFF_AT + b * S + q * 100 + t];
    __syncthreads();
    const float* eob = EO + ((size_t)b * S + q * 100) * TWOH;
    float c = 0.f;
    #pragma unroll 10
    for (int s = 0; s < 100; s++) c += sa[s] * eob[(size_t)s * TWOH + t];
    g_ctxpart[(size_t)blk * TWOH + t] = c;
}

// ---------------------------------------------------------------------------
// K3d: combine ctx partials + gen_p. grid=(B), 512thr.
// ---------------------------------------------------------------------------
__global__ void k3d_ctx(const float* __restrict__ gp_wh, float* __restrict__ out)
{
    const int b = blockIdx.x;
    const int t = threadIdx.x;
    __shared__ float red[512];
    float c = g_ctxpart[(size_t)(b * 4 + 0) * TWOH + t]
            + g_ctxpart[(size_t)(b * 4 + 1) * TWOH + t]
            + g_ctxpart[(size_t)(b * 4 + 2) * TWOH + t]
            + g_ctxpart[(size_t)(b * 4 + 3) * TWOH + t];
    out[OFF_CTX + b * TWOH + t] = c;
    red[t] = gp_wh[t] * c;
    __syncthreads();
    for (int off = 256; off > 0; off >>= 1) {
        if (t < off) red[t] += red[t + off];
        __syncthreads();
    }
    if (t == 0) out[OFF_GP + b] = sigf(red[0] + g_gpart[b]);
}

// ---------------------------------------------------------------------------
// K3b: hidden = relu(out_w1 @ [h_t, ctx] + b1), tiled 64x64. grid=(4,2), 256thr.
// ---------------------------------------------------------------------------
__global__ void k3b_hidden(
    const float* __restrict__ out_w1, const float* __restrict__ out_b1,
    const float* __restrict__ out)
{
    __shared__ __align__(16) float As[16][68];
    __shared__ __align__(16) float Ws[16][68];

    const int tid = threadIdx.x;
    const int tx = tid & 15, ty = tid >> 4;
    const int rl = tid >> 2, kq = tid & 3;
    const int m0 = blockIdx.y * 64;
    const int n0 = blockIdx.x * 64;

    float acc[4][4];
    #pragma unroll
    for (int a = 0; a < 4; a++)
        #pragma unroll
        for (int c = 0; c < 4; c++) acc[a][c] = 0.f;

    for (int kt = 0; kt < 48; kt++) {
        const int k = kt * 16 + kq * 4;
        const int m = m0 + rl;
        float4 av = (k < H)
            ? *(const float4*)(out + OFF_HT + m * H + k)
            : *(const float4*)(out + OFF_CTX + m * TWOH + (k - H));
        float4 wv = *(const float4*)(out_w1 + (size_t)(n0 + rl) * (H + TWOH) + k);
        __syncthreads();
        As[kq * 4 + 0][rl] = av.x; As[kq * 4 + 1][rl] = av.y;
        As[kq * 4 + 2][rl] = av.z; As[kq * 4 + 3][rl] = av.w;
        Ws[kq * 4 + 0][rl] = wv.x; Ws[kq * 4 + 1][rl] = wv.y;
        Ws[kq * 4 + 2][rl] = wv.z; Ws[kq * 4 + 3][rl] = wv.w;
        __syncthreads();
        #pragma unroll
        for (int kk = 0; kk < 16; kk++) {
            float ar[4], wr[4];
            *(float4*)ar = *(const float4*)&As[kk][ty * 4];
            *(float4*)wr = *(const float4*)&Ws[kk][tx * 4];
            #pragma unroll
            for (int mi = 0; mi < 4; mi++)
                #pragma unroll
                for (int jj = 0; jj < 4; jj++)
                    acc[mi][jj] += ar[mi] * wr[jj];
        }
    }

    #pragma unroll
    for (int mi = 0; mi < 4; mi++) {
        const int m = m0 + ty * 4 + mi;
        #pragma unroll
        for (int jj = 0; jj < 4; jj++) {
            const int o = n0 + tx * 4 + jj;
            g_hidden[m * H + o] = fmaxf(acc[mi][jj] + out_b1[o], 0.f);
        }
    }
}

// ---------------------------------------------------------------------------
// K4: logits GEMM, fp16 two-product; epilogue stores exp(logit) and
// accumulates per-row vocab sum-exp (no max shift; logits are O(1)).
// ---------------------------------------------------------------------------
#define K4_BUF 40960
#define K4_AH 0
#define K4_AL 10240
#define K4_BH 20480
#define K4_SMEM 81920

__global__ void __launch_bounds__(512, 1) k4_mma(
    const float* __restrict__ W2, const float* __restrict__ b2)
{
    extern __shared__ char smem[];

    const int tid = threadIdx.x;
    const int w = tid >> 5, lane = tid & 31;
    const int g = lane >> 2, t = lane & 3;
    const int wm = w & 3, wn = w >> 2;
    const int j0 = blockIdx.x * 256;

    const int ar = tid >> 3, aq = tid & 7;
    const int br = tid >> 3, bq = tid & 7;

    float c[2][8][4];
    #pragma unroll
    for (int mi = 0; mi < 2; mi++)
        #pragma unroll
        for (int ni = 0; ni < 8; ni++)
            #pragma unroll
            for (int q = 0; q < 4; q++) c[mi][ni][q] = 0.f;

    float4 avv[2], bvv[4];

    #pragma unroll
    for (int i = 0; i < 2; i++)
        avv[i] = *(const float4*)(g_hidden + (size_t)(i * 64 + ar) * H + aq * 4);
    #pragma unroll
    for (int i = 0; i < 4; i++) {
        int j = j0 + i * 64 + br;
        bvv[i] = (j < V) ? *(const float4*)(W2 + (size_t)j * H + bq * 4)
                         : make_float4(0.f, 0.f, 0.f, 0.f);
    }
    {
        unsigned* AHp = (unsigned*)(smem + K4_AH);
        unsigned* ALp = (unsigned*)(smem + K4_AL);
        unsigned* BHp = (unsigned*)(smem + K4_BH);
        #pragma unroll
        for (int i = 0; i < 2; i++) {
            unsigned h0_, l0_, h1_, l1_;
            splitpack(avv[i].x, avv[i].y, h0_, l0_);
            splitpack(avv[i].z, avv[i].w, h1_, l1_);
            *(uint2*)(AHp + (i * 64 + ar) * K2P + aq * 2) = make_uint2(h0_, h1_);
            *(uint2*)(ALp + (i * 64 + ar) * K2P + aq * 2) = make_uint2(l0_, l1_);
        }
        #pragma unroll
        for (int i = 0; i < 4; i++) {
            *(uint2*)(BHp + (i * 64 + br) * K2P + bq * 2) =
                make_uint2(packhi(bvv[i].x, bvv[i].y), packhi(bvv[i].z, bvv[i].w));
        }
    }
    __syncthreads();

    for (int kt = 0; kt < 8; kt++) {
        char* bufc = smem + (kt & 1) * K4_BUF;
        if (kt < 7) {
            const int k0 = (kt + 1) * 32;
            #pragma unroll
            for (int i = 0; i < 2; i++)
                avv[i] = *(const float4*)(g_hidden + (size_t)(i * 64 + ar) * H + k0 + aq * 4);
            #pragma unroll
            for (int i = 0; i < 4; i++) {
                int j = j0 + i * 64 + br;
                bvv[i] = (j < V) ? *(const float4*)(W2 + (size_t)j * H + k0 + bq * 4)
                                 : make_float4(0.f, 0.f, 0.f, 0.f);
            }
        }

        unsigned* AHc = (unsigned*)(bufc + K4_AH);
        unsigned* ALc = (unsigned*)(bufc + K4_AL);
        unsigned* BHc = (unsigned*)(bufc + K4_BH);
        #pragma unroll
        for (int s = 0; s < 2; s++) {
            unsigned ah[2][4], al[2][4];
            #pragma unroll
            for (int mi = 0; mi < 2; mi++) {
                const unsigned* pa = AHc + (wm * 32 + mi * 16 + g) * K2P + s * 8 + t;
                ah[mi][0] = pa[0]; ah[mi][1] = pa[8 * K2P];
                ah[mi][2] = pa[4]; ah[mi][3] = pa[8 * K2P + 4];
                const unsigned* pl = ALc + (wm * 32 + mi * 16 + g) * K2P + s * 8 + t;
                al[mi][0] = pl[0]; al[mi][1] = pl[8 * K2P];
                al[mi][2] = pl[4]; al[mi][3] = pl[8 * K2P + 4];
            }
            #pragma unroll
            for (int ni = 0; ni < 8; ni++) {
                const unsigned* pb = BHc + (wn * 64 + ni * 8 + g) * K2P + s * 8 + t;
                unsigned bh0 = pb[0], bh1 = pb[4];
                #pragma unroll
                for (int mi = 0; mi < 2; mi++) {
                    mma16(c[mi][ni], ah[mi], bh0, bh1);
                    mma16(c[mi][ni], al[mi], bh0, bh1);
                }
            }
        }

        if (kt < 7) {
            char* bufn = smem + ((kt + 1) & 1) * K4_BUF;
            unsigned* AHn = (unsigned*)(bufn + K4_AH);
            unsigned* ALn = (unsigned*)(bufn + K4_AL);
            unsigned* BHn = (unsigned*)(bufn + K4_BH);
            #pragma unroll
            for (int i = 0; i < 2; i++) {
                unsigned h0_, l0_, h1_, l1_;
                splitpack(avv[i].x, avv[i].y, h0_, l0_);
                splitpack(avv[i].z, avv[i].w, h1_, l1_);
                *(uint2*)(AHn + (i * 64 + ar) * K2P + aq * 2) = make_uint2(h0_, h1_);
                *(uint2*)(ALn + (i * 64 + ar) * K2P + aq * 2) = make_uint2(l0_, l1_);
            }
            #pragma unroll
            for (int i = 0; i < 4; i++) {
                *(uint2*)(BHn + (i * 64 + br) * K2P + bq * 2) =
                    make_uint2(packhi(bvv[i].x, bvv[i].y), packhi(bvv[i].z, bvv[i].w));
            }
        }
        __syncthreads();
    }

    // epilogue: store exp(logit) + per-row partial sum-exp
    float* ssum = (float*)smem;
    #pragma unroll
    for (int mi = 0; mi < 2; mi++) {
        #pragma unroll
        for (int hf = 0; hf < 2; hf++) {
            const int r = wm * 32 + mi * 16 + hf * 8 + g;
            float ps = 0.f;
            #pragma unroll
            for (int ni = 0; ni < 8; ni++) {
                const int j = j0 + wn * 64 + ni * 8 + t * 2;
                if (j < V) {
                    float e0 = expf(c[mi][ni][hf * 2 + 0] + b2[j]);
                    float e1 = expf(c[mi][ni][hf * 2 + 1] + b2[j + 1]);
                    *(float2*)(g_logits + (size_t)r * V + j) = make_float2(e0, e1);
                    ps += e0 + e1;
                }
            }
            ps += __shfl_xor_sync(0xffffffffu, ps, 1);
            ps += __shfl_xor_sync(0xffffffffu, ps, 2);
            if (t == 0) ssum[r * 4 + wn] = ps;
        }
    }
    __syncthreads();
    if (tid < 128) {
        float s2 = ssum[tid * 4] + ssum[tid * 4 + 1] + ssum[tid * 4 + 2] + ssum[tid * 4 + 3];
        atomicAdd(&g_psum[tid], s2);
    }
}

// ---------------------------------------------------------------------------
// K5b: final_dist = expstore / sumexp * gen_p, zero OOV tail.
// ---------------------------------------------------------------------------
__global__ void k5b_final(float* __restrict__ out)
{
    const int i = blockIdx.x * 256 + threadIdx.x;
    if (i >= B * VO) return;
    const int b = i / VO;
    const int c = i - b * VO;
    float v = 0.f;
    if (c < V) {
        const float gp = out[OFF_GP + b];
        v = g_logits[(size_t)b * V + c] * (1.f / g_psum[b]) * gp;
    }
    out[i] = v;
}

__global__ void k5c_scatter(const int* __restrict__ ewo, float* __restrict__ out)
{
    const int i = blockIdx.x * 256 + threadIdx.x;
    if (i >= B * S) return;
    const int b = i / S;
    const float gp = out[OFF_GP + b];
    const float a = out[OFF_AT + i];
    atomicAdd(out + (size_t)b * VO + ewo[i], a * (1.f - gp));
}

// ---------------------------------------------------------------------------
extern "C" void kernel_launch(void* const* d_in, const int* in_sizes, int n_in,
                              void* d_out, int out_size)
{
    const int*   idx      = (const int*)  d_in[0];
    const float* h0       = (const float*)d_in[1];
    const float* c0       = (const float*)d_in[2];
    const float* EO       = (const float*)d_in[3];
    const int*   emask    = (const int*)  d_in[4];
    const float* ctxv     = (const float*)d_in[5];
    const int*   ewo      = (const int*)  d_in[7];
    const float* coverage = (const float*)d_in[8];
    const float* emb      = (const float*)d_in[9];
    const float* Wi       = (const float*)d_in[10];
    const float* bi       = (const float*)d_in[11];
    const float* W_ih     = (const float*)d_in[12];
    const float* W_hh     = (const float*)d_in[13];
    const float* b_ih     = (const float*)d_in[14];
    const float* b_hh     = (const float*)d_in[15];
    const float* att_wh   = (const float*)d_in[16];
    const float* att_ws   = (const float*)d_in[17];
    const float* att_wc   = (const float*)d_in[18];
    const float* att_bc   = (const float*)d_in[19];
    const float* att_v    = (const float*)d_in[20];
    const float* gp_wh    = (const float*)d_in[21];
    const float* gp_bh    = (const float*)d_in[22];
    const float* gp_ws    = (const float*)d_in[23];
    const float* gp_bs    = (const float*)d_in[24];
    const float* gp_wx    = (const float*)d_in[25];
    const float* gp_bx    = (const float*)d_in[26];
    const float* out_w1   = (const float*)d_in[27];
    const float* out_b1   = (const float*)d_in[28];
    const float* out_w2   = (const float*)d_in[29];
    const float* out_b2   = (const float*)d_in[30];
    float* out = (float*)d_out;

    static int attr_done = 0;
    if (!attr_done) {
        cudaFuncSetAttribute(k2_mma, cudaFuncAttributeMaxDynamicSharedMemorySize, K2_SMEM);
        cudaFuncSetAttribute(k4_mma, cudaFuncAttributeMaxDynamicSharedMemorySize, K4_SMEM);
        attr_done = 1;
    }

    k0_wh<<<512, 256>>>(att_wh);
    k1_lstm<<<B, 256>>>(idx, h0, c0, ctxv, emb, Wi, bi, W_ih, W_hh, b_ih, b_hh,
                        att_ws, att_bc, gp_ws, gp_bs, gp_wx, gp_bx, gp_bh, out);
    k2_mma<<<(B * S) / 64, 512, K2_SMEM>>>(EO, att_wc, att_v, coverage, emask);
    k3a_softmax<<<B, 512>>>(coverage, out);
    k3c_ctxpart<<<B * 4, 512>>>(EO, out);
    k3d_ctx<<<B, 512>>>(gp_wh, out);
    {
        dim3 g3b(4, 2);
        k3b_hidden<<<g3b, 256>>>(out_w1, out_b1, out);
    }
    k4_mma<<<(V + 255) / 256, 512, K4_SMEM>>>(out_w2, out_b2);
    k5b_final<<<(B * VO + 255) / 256, 256>>>(out);
    k5c_scatter<<<(B * S + 255) / 256, 256>>>(ewo, out);
}

// round 11
// speedup vs baseline: 1.3020x; 1.0172x over previous
#include <cuda_runtime.h>
#include <cuda_fp16.h>
#include <math.h>

#define B 128
#define S 400
#define H 256
#define E 128
#define V 50000
#define OOV 50
#define TWOH 512
#define VO (V + OOV)

#define OFF_HT   (B * VO)
#define OFF_CT   (OFF_HT + B * H)
#define OFF_CTX  (OFF_CT + B * H)
#define OFF_AT   (OFF_CTX + B * TWOH)
#define OFF_GP   (OFF_AT + B * S)
#define OFF_COV  (OFF_GP + B)

__device__ float g_decbase[B * TWOH];
__device__ float g_gpart[B];
__device__ float g_et[B * S];
__device__ float g_hidden[B * H];
__device__ float g_logits[(size_t)B * V];   // holds exp(logit) after k4
__device__ float g_psum[B];
__device__ float g_ctxpart[B * 4 * TWOH];
// Wh pre-packed fp16 hi, k-pair packed, chunked: [16 chunks][512 n][16 kp]
__device__ unsigned g_WhHi[16 * 512 * 16];

__device__ __forceinline__ float sigf(float x) { return 1.0f / (1.0f + expf(-x)); }

__device__ __forceinline__ float wred(float a) {
    a += __shfl_xor_sync(0xffffffffu, a, 16);
    a += __shfl_xor_sync(0xffffffffu, a, 8);
    a += __shfl_xor_sync(0xffffffffu, a, 4);
    a += __shfl_xor_sync(0xffffffffu, a, 2);
    a += __shfl_xor_sync(0xffffffffu, a, 1);
    return a;
}

__device__ __forceinline__ unsigned packhi(float x, float y) {
    __half hx = __float2half_rn(x), hy = __float2half_rn(y);
    return ((unsigned)__half_as_ushort(hy) << 16) | (unsigned)__half_as_ushort(hx);
}

__device__ __forceinline__ void mma16(float c[4], const unsigned a[4], unsigned b0, unsigned b1) {
    asm("mma.sync.aligned.m16n8k16.row.col.f32.f16.f16.f32 "
        "{%0,%1,%2,%3}, {%4,%5,%6,%7}, {%8,%9}, {%0,%1,%2,%3};"
        : "+f"(c[0]), "+f"(c[1]), "+f"(c[2]), "+f"(c[3])
        : "r"(a[0]), "r"(a[1]), "r"(a[2]), "r"(a[3]), "r"(b0), "r"(b1));
}

// ---------------------------------------------------------------------------
// K0: pre-pack Wh fp16 hi, k-pair packed; zero g_psum. grid=(512), 256thr.
// ---------------------------------------------------------------------------
__global__ void k0_wh(const float* __restrict__ Wh)
{
    int idx = blockIdx.x * 256 + threadIdx.x;
    int n = idx >> 8;
    int kpg = idx & 255;
    int k = kpg * 2;
    int c = k >> 5, kp = (k & 31) >> 1;
    float2 v = *(const float2*)(Wh + (size_t)n * TWOH + k);
    g_WhHi[(c * 512 + n) * 16 + kp] = packhi(v.x, v.y);
    if (blockIdx.x == 0 && threadIdx.x < B) g_psum[threadIdx.x] = 0.f;
}

// ---------------------------------------------------------------------------
// K1: embedding + input proj + LSTM + decbase + gen_p partial. grid=(B), 256thr.
// ---------------------------------------------------------------------------
__global__ void k1_lstm(
    const int* __restrict__ idx, const float* __restrict__ h0, const float* __restrict__ c0,
    const float* __restrict__ ctxv, const float* __restrict__ emb,
    const float* __restrict__ Wi, const float* __restrict__ bi,
    const float* __restrict__ W_ih, const float* __restrict__ W_hh,
    const float* __restrict__ b_ih, const float* __restrict__ b_hh,
    const float* __restrict__ att_ws, const float* __restrict__ att_bc,
    const float* __restrict__ gp_ws, const float* __restrict__ gp_bs,
    const float* __restrict__ gp_wx, const float* __restrict__ gp_bx,
    const float* __restrict__ gp_bh,
    float* __restrict__ out)
{
    const int b = blockIdx.x;
    const int tid = threadIdx.x;
    const int w = tid >> 5, lane = tid & 31;

    __shared__ float s_in[TWOH + E];
    __shared__ float s_x[E];
    __shared__ float s_h0[H];
    __shared__ float s_gates[4 * H];
    __shared__ float s_st[TWOH];
    __shared__ float s_red[256];

    for (int k = tid; k < TWOH; k += 256) s_in[k] = ctxv[b * TWOH + k];
    if (tid < E) s_in[TWOH + tid] = emb[(size_t)idx[b] * E + tid];
    s_h0[tid] = h0[b * H + tid];
    __syncthreads();

    for (int o = w * 16; o < (w + 1) * 16; o++) {
        const float* wr = Wi + (size_t)o * (TWOH + E);
        float a = 0.f;
        for (int k = lane; k < TWOH + E; k += 32) a += wr[k] * s_in[k];
        a = wred(a);
        if (lane == 0) s_x[o] = a + bi[o];
    }
    __syncthreads();

    for (int o = w * 128; o < (w + 1) * 128; o++) {
        const float* wi_ = W_ih + (size_t)o * E;
        const float* wh_ = W_hh + (size_t)o * H;
        float a = 0.f;
        for (int k = lane; k < E; k += 32) a += wi_[k] * s_x[k];
        for (int k = lane; k < H; k += 32) a += wh_[k] * s_h0[k];
        a = wred(a);
        if (lane == 0) s_gates[o] = a + b_ih[o] + b_hh[o];
    }
    __syncthreads();

    {
        float ig = sigf(s_gates[tid]);
        float fg = sigf(s_gates[H + tid]);
        float gg = tanhf(s_gates[2 * H + tid]);
        float og = sigf(s_gates[3 * H + tid]);
        float c = fg * c0[b * H + tid] + ig * gg;
        float h = og * tanhf(c);
        out[OFF_HT + b * H + tid] = h;
        out[OFF_CT + b * H + tid] = c;
        s_st[tid] = h;
        s_st[H + tid] = c;
    }
    __syncthreads();

    for (int o = w * 64; o < (w + 1) * 64; o++) {
        const float* wr = att_ws + (size_t)o * TWOH;
        float a = 0.f;
        for (int k = lane; k < TWOH; k += 32) a += wr[k] * s_st[k];
        a = wred(a);
        if (lane == 0) g_decbase[b * TWOH + o] = a + att_bc[o];
    }

    float p = 0.f;
    for (int k = tid; k < TWOH; k += 256) p += gp_ws[k] * s_st[k];
    if (tid < E) p += gp_wx[tid] * s_x[tid];
    s_red[tid] = p;
    __syncthreads();
    for (int off = 128; off > 0; off >>= 1) {
        if (tid < off) s_red[tid] += s_red[tid + off];
        __syncthreads();
    }
    if (tid == 0) g_gpart[b] = s_red[0] + gp_bs[0] + gp_bx[0] + gp_bh[0];
}

// ---------------------------------------------------------------------------
// K2: attention scores, SINGLE-product fp16 mma (fp32 acc), double-buffered
// register-prefetch pipeline.
// Block: 64 rows x 512 n, K=512 in 16 chunks of 32. 512thr = 16 warps (2m x 8n).
// ---------------------------------------------------------------------------
#define K2P 20
#define K2_AH 0
#define K2_BH 5120
#define K2_BUF 46080
#define K2_SV  92160
#define K2_SWC 94208
#define K2_SDB 96256
#define K2_EP  100352
#define K2_SMEM 102400

__global__ void __launch_bounds__(512, 1) k2_mma(
    const float* __restrict__ EO,
    const float* __restrict__ att_wc, const float* __restrict__ att_v,
    const float* __restrict__ coverage, const int* __restrict__ mask)
{
    extern __shared__ char smem[];
    float* sv  = (float*)(smem + K2_SV);
    float* swc = (float*)(smem + K2_SWC);
    float* sdb = (float*)(smem + K2_SDB);
    float* ep  = (float*)(smem + K2_EP);

    const int tid = threadIdx.x;
    const int w = tid >> 5, lane = tid & 31;
    const int g = lane >> 2, t = lane & 3;
    const int wm = w & 1, wn = w >> 1;
    const int row0 = blockIdx.x * 64;
    const int b0 = row0 / S;
    const int b1e = (row0 + 63) / S;

    sv[tid] = att_v[tid];
    swc[tid] = att_wc[tid];
    sdb[tid] = g_decbase[b0 * TWOH + tid];
    sdb[512 + tid] = g_decbase[b1e * TWOH + tid];

    const int ar = tid >> 3, aq = tid & 7;
    const int bn = tid >> 2, bkq = tid & 3;
    const float* aptr = EO + (size_t)(row0 + ar) * TWOH + aq * 4;

    float c[2][8][4];
    #pragma unroll
    for (int mi = 0; mi < 2; mi++)
        #pragma unroll
        for (int ni = 0; ni < 8; ni++)
            #pragma unroll
            for (int q = 0; q < 4; q++) c[mi][ni][q] = 0.f;

    float4 av;
    uint4 bv[4];

    av = *(const float4*)(aptr);
    #pragma unroll
    for (int i = 0; i < 4; i++)
        bv[i] = *(const uint4*)(g_WhHi + ((size_t)(i * 128 + bn) * 16 + bkq * 4));
    {
        *(uint2*)((unsigned*)(smem + K2_AH) + ar * K2P + aq * 2) =
            make_uint2(packhi(av.x, av.y), packhi(av.z, av.w));
        unsigned* BHp = (unsigned*)(smem + K2_BH);
        #pragma unroll
        for (int i = 0; i < 4; i++)
            *(uint4*)(BHp + (i * 128 + bn) * K2P + bkq * 4) = bv[i];
    }
    __syncthreads();

    for (int kt = 0; kt < 16; kt++) {
        char* bufc = smem + (kt & 1) * K2_BUF;
        if (kt < 15) {
            av = *(const float4*)(aptr + (kt + 1) * 32);
            #pragma unroll
            for (int i = 0; i < 4; i++)
                bv[i] = *(const uint4*)(g_WhHi + ((size_t)((kt + 1) * 512 + i * 128 + bn) * 16 + bkq * 4));
        }

        unsigned* AHc = (unsigned*)(bufc + K2_AH);
        unsigned* BHc = (unsigned*)(bufc + K2_BH);
        #pragma unroll
        for (int s = 0; s < 2; s++) {
            unsigned ah[2][4];
            #pragma unroll
            for (int mi = 0; mi < 2; mi++) {
                const unsigned* pa = AHc + (wm * 32 + mi * 16 + g) * K2P + s * 8 + t;
                ah[mi][0] = pa[0]; ah[mi][1] = pa[8 * K2P];
                ah[mi][2] = pa[4]; ah[mi][3] = pa[8 * K2P + 4];
            }
            #pragma unroll
            for (int ni = 0; ni < 8; ni++) {
                const unsigned* pb = BHc + (wn * 64 + ni * 8 + g) * K2P + s * 8 + t;
                unsigned bh0 = pb[0], bh1 = pb[4];
                #pragma unroll
                for (int mi = 0; mi < 2; mi++)
                    mma16(c[mi][ni], ah[mi], bh0, bh1);
            }
        }

        if (kt < 15) {
            char* bufn = smem + ((kt + 1) & 1) * K2_BUF;
            *(uint2*)((unsigned*)(bufn + K2_AH) + ar * K2P + aq * 2) =
                make_uint2(packhi(av.x, av.y), packhi(av.z, av.w));
            unsigned* BHn = (unsigned*)(bufn + K2_BH);
            #pragma unroll
            for (int i = 0; i < 4; i++)
                *(uint4*)(BHn + (i * 128 + bn) * K2P + bkq * 4) = bv[i];
        }
        __syncthreads();
    }

    #pragma unroll
    for (int mi = 0; mi < 2; mi++) {
        #pragma unroll
        for (int hf = 0; hf < 2; hf++) {
            const int rl = wm * 32 + mi * 16 + hf * 8 + g;
            const int r = row0 + rl;
            const int dbo = (r / S != b0) ? 512 : 0;
            const float cov = coverage[r];
            float acc = 0.f;
            #pragma unroll
            for (int ni = 0; ni < 8; ni++) {
                const int j = wn * 64 + ni * 8 + t * 2;
                float v0 = c[mi][ni][hf * 2 + 0] + sdb[dbo + j] + cov * swc[j];
                float v1 = c[mi][ni][hf * 2 + 1] + sdb[dbo + j + 1] + cov * swc[j + 1];
                acc += sv[j] * tanhf(v0) + sv[j + 1] * tanhf(v1);
            }
            acc += __shfl_xor_sync(0xffffffffu, acc, 1);
            acc += __shfl_xor_sync(0xffffffffu, acc, 2);
            if (t == 0) ep[rl * 8 + wn] = acc;
        }
    }
    __syncthreads();
    if (tid < 64) {
        float sacc = 0.f;
        #pragma unroll
        for (int q = 0; q < 8; q++) sacc += ep[tid * 8 + q];
        const int r = row0 + tid;
        g_et[r] = (mask[r] == 0) ? -1e30f : sacc;
    }
}

// ---------------------------------------------------------------------------
// K3a: masked softmax over S -> a_t, next_coverage. grid=(B), 512thr.
// ---------------------------------------------------------------------------
__global__ void k3a_softmax(const float* __restrict__ coverage, float* __restrict__ out)
{
    const int b = blockIdx.x;
    const int t = threadIdx.x;
    __shared__ float red[512];

    float e = (t < S) ? g_et[b * S + t] : -1e30f;
    red[t] = e;
    __syncthreads();
    for (int off = 256; off > 0; off >>= 1) {
        if (t < off) red[t] = fmaxf(red[t], red[t + off]);
        __syncthreads();
    }
    const float mx = red[0];
    __syncthreads();

    float ex = (t < S) ? expf(e - mx) : 0.f;
    red[t] = ex;
    __syncthreads();
    for (int off = 256; off > 0; off >>= 1) {
        if (t < off) red[t] += red[t + off];
        __syncthreads();
    }
    const float inv = 1.f / red[0];

    if (t < S) {
        float a = ex * inv;
        out[OFF_AT + b * S + t] = a;
        out[OFF_COV + b * S + t] = coverage[b * S + t] + a;
    }
}

// ---------------------------------------------------------------------------
// K3c: ctx partials. grid=(B*4), 512thr.
// ---------------------------------------------------------------------------
__global__ void k3c_ctxpart(const float* __restrict__ EO, const float* __restrict__ out)
{
    const int blk = blockIdx.x;
    const int b = blk >> 2, q = blk & 3;
    const int t = threadIdx.x;
    __shared__ float sa[100];
    if (t < 100) sa[t] = out[OFF_AT + b * S + q * 100 + t];
    __syncthreads();
    const float* eob = EO + ((size_t)b * S + q * 100) * TWOH;
    float c = 0.f;
    #pragma unroll 10
    for (int s = 0; s < 100; s++) c += sa[s] * eob[(size_t)s * TWOH + t];
    g_ctxpart[(size_t)blk * TWOH + t] = c;
}

// ---------------------------------------------------------------------------
// K3d: combine ctx partials + gen_p. grid=(B), 512thr.
// ---------------------------------------------------------------------------
__global__ void k3d_ctx(const float* __restrict__ gp_wh, float* __restrict__ out)
{
    const int b = blockIdx.x;
    const int t = threadIdx.x;
    __shared__ float red[512];
    float c = g_ctxpart[(size_t)(b * 4 + 0) * TWOH + t]
            + g_ctxpart[(size_t)(b * 4 + 1) * TWOH + t]
            + g_ctxpart[(size_t)(b * 4 + 2) * TWOH + t]
            + g_ctxpart[(size_t)(b * 4 + 3) * TWOH + t];
    out[OFF_CTX + b * TWOH + t] = c;
    red[t] = gp_wh[t] * c;
    __syncthreads();
    for (int off = 256; off > 0; off >>= 1) {
        if (t < off) red[t] += red[t + off];
        __syncthreads();
    }
    if (t == 0) out[OFF_GP + b] = sigf(red[0] + g_gpart[b]);
}

// ---------------------------------------------------------------------------
// K3b: hidden = relu(out_w1 @ [h_t, ctx] + b1), tiled 64x64. grid=(4,2), 256thr.
// ---------------------------------------------------------------------------
__global__ void k3b_hidden(
    const float* __restrict__ out_w1, const float* __restrict__ out_b1,
    const float* __restrict__ out)
{
    __shared__ __align__(16) float As[16][68];
    __shared__ __align__(16) float Ws[16][68];

    const int tid = threadIdx.x;
    const int tx = tid & 15, ty = tid >> 4;
    const int rl = tid >> 2, kq = tid & 3;
    const int m0 = blockIdx.y * 64;
    const int n0 = blockIdx.x * 64;

    float acc[4][4];
    #pragma unroll
    for (int a = 0; a < 4; a++)
        #pragma unroll
        for (int c = 0; c < 4; c++) acc[a][c] = 0.f;

    for (int kt = 0; kt < 48; kt++) {
        const int k = kt * 16 + kq * 4;
        const int m = m0 + rl;
        float4 av = (k < H)
            ? *(const float4*)(out + OFF_HT + m * H + k)
            : *(const float4*)(out + OFF_CTX + m * TWOH + (k - H));
        float4 wv = *(const float4*)(out_w1 + (size_t)(n0 + rl) * (H + TWOH) + k);
        __syncthreads();
        As[kq * 4 + 0][rl] = av.x; As[kq * 4 + 1][rl] = av.y;
        As[kq * 4 + 2][rl] = av.z; As[kq * 4 + 3][rl] = av.w;
        Ws[kq * 4 + 0][rl] = wv.x; Ws[kq * 4 + 1][rl] = wv.y;
        Ws[kq * 4 + 2][rl] = wv.z; Ws[kq * 4 + 3][rl] = wv.w;
        __syncthreads();
        #pragma unroll
        for (int kk = 0; kk < 16; kk++) {
            float ar[4], wr[4];
            *(float4*)ar = *(const float4*)&As[kk][ty * 4];
            *(float4*)wr = *(const float4*)&Ws[kk][tx * 4];
            #pragma unroll
            for (int mi = 0; mi < 4; mi++)
                #pragma unroll
                for (int jj = 0; jj < 4; jj++)
                    acc[mi][jj] += ar[mi] * wr[jj];
        }
    }

    #pragma unroll
    for (int mi = 0; mi < 4; mi++) {
        const int m = m0 + ty * 4 + mi;
        #pragma unroll
        for (int jj = 0; jj < 4; jj++) {
            const int o = n0 + tx * 4 + jj;
            g_hidden[m * H + o] = fmaxf(acc[mi][jj] + out_b1[o], 0.f);
        }
    }
}

// ---------------------------------------------------------------------------
// K4: logits GEMM, SINGLE-product fp16 mma; epilogue stores exp(logit) and
// accumulates per-row vocab sum-exp. Double-buffered register prefetch.
// Block 128m x 256n, K=256 (8 chunks of 32). 512thr = 16 warps (4m x 4n).
// Per buffer: AH [128][20] (10240B) | BH [256][20] (20480B).
// ---------------------------------------------------------------------------
#define K4_AH 0
#define K4_BH 10240
#define K4_BUF 30720
#define K4_SMEM 61440

__global__ void __launch_bounds__(512, 1) k4_mma(
    const float* __restrict__ W2, const float* __restrict__ b2)
{
    extern __shared__ char smem[];

    const int tid = threadIdx.x;
    const int w = tid >> 5, lane = tid & 31;
    const int g = lane >> 2, t = lane & 3;
    const int wm = w & 3, wn = w >> 2;
    const int j0 = blockIdx.x * 256;

    const int ar = tid >> 3, aq = tid & 7;
    const int br = tid >> 3, bq = tid & 7;

    float c[2][8][4];
    #pragma unroll
    for (int mi = 0; mi < 2; mi++)
        #pragma unroll
        for (int ni = 0; ni < 8; ni++)
            #pragma unroll
            for (int q = 0; q < 4; q++) c[mi][ni][q] = 0.f;

    float4 avv[2], bvv[4];

    #pragma unroll
    for (int i = 0; i < 2; i++)
        avv[i] = *(const float4*)(g_hidden + (size_t)(i * 64 + ar) * H + aq * 4);
    #pragma unroll
    for (int i = 0; i < 4; i++) {
        int j = j0 + i * 64 + br;
        bvv[i] = (j < V) ? *(const float4*)(W2 + (size_t)j * H + bq * 4)
                         : make_float4(0.f, 0.f, 0.f, 0.f);
    }
    {
        unsigned* AHp = (unsigned*)(smem + K4_AH);
        unsigned* BHp = (unsigned*)(smem + K4_BH);
        #pragma unroll
        for (int i = 0; i < 2; i++)
            *(uint2*)(AHp + (i * 64 + ar) * K2P + aq * 2) =
                make_uint2(packhi(avv[i].x, avv[i].y), packhi(avv[i].z, avv[i].w));
        #pragma unroll
        for (int i = 0; i < 4; i++)
            *(uint2*)(BHp + (i * 64 + br) * K2P + bq * 2) =
                make_uint2(packhi(bvv[i].x, bvv[i].y), packhi(bvv[i].z, bvv[i].w));
    }
    __syncthreads();

    for (int kt = 0; kt < 8; kt++) {
        char* bufc = smem + (kt & 1) * K4_BUF;
        if (kt < 7) {
            const int k0 = (kt + 1) * 32;
            #pragma unroll
            for (int i = 0; i < 2; i++)
                avv[i] = *(const float4*)(g_hidden + (size_t)(i * 64 + ar) * H + k0 + aq * 4);
            #pragma unroll
            for (int i = 0; i < 4; i++) {
                int j = j0 + i * 64 + br;
                bvv[i] = (j < V) ? *(const float4*)(W2 + (size_t)j * H + k0 + bq * 4)
                                 : make_float4(0.f, 0.f, 0.f, 0.f);
            }
        }

        unsigned* AHc = (unsigned*)(bufc + K4_AH);
        unsigned* BHc = (unsigned*)(bufc + K4_BH);
        #pragma unroll
        for (int s = 0; s < 2; s++) {
            unsigned ah[2][4];
            #pragma unroll
            for (int mi = 0; mi < 2; mi++) {
                const unsigned* pa = AHc + (wm * 32 + mi * 16 + g) * K2P + s * 8 + t;
                ah[mi][0] = pa[0]; ah[mi][1] = pa[8 * K2P];
                ah[mi][2] = pa[4]; ah[mi][3] = pa[8 * K2P + 4];
            }
            #pragma unroll
            for (int ni = 0; ni < 8; ni++) {
                const unsigned* pb = BHc + (wn * 64 + ni * 8 + g) * K2P + s * 8 + t;
                unsigned bh0 = pb[0], bh1 = pb[4];
                #pragma unroll
                for (int mi = 0; mi < 2; mi++)
                    mma16(c[mi][ni], ah[mi], bh0, bh1);
            }
        }

        if (kt < 7) {
            char* bufn = smem + ((kt + 1) & 1) * K4_BUF;
            unsigned* AHn = (unsigned*)(bufn + K4_AH);
            unsigned* BHn = (unsigned*)(bufn + K4_BH);
            #pragma unroll
            for (int i = 0; i < 2; i++)
                *(uint2*)(AHn + (i * 64 + ar) * K2P + aq * 2) =
                    make_uint2(packhi(avv[i].x, avv[i].y), packhi(avv[i].z, avv[i].w));
            #pragma unroll
            for (int i = 0; i < 4; i++)
                *(uint2*)(BHn + (i * 64 + br) * K2P + bq * 2) =
                    make_uint2(packhi(bvv[i].x, bvv[i].y), packhi(bvv[i].z, bvv[i].w));
        }
        __syncthreads();
    }

    // epilogue: store exp(logit) + per-row partial sum-exp
    float* ssum = (float*)smem;
    #pragma unroll
    for (int mi = 0; mi < 2; mi++) {
        #pragma unroll
        for (int hf = 0; hf < 2; hf++) {
            const int r = wm * 32 + mi * 16 + hf * 8 + g;
            float ps = 0.f;
            #pragma unroll
            for (int ni = 0; ni < 8; ni++) {
                const int j = j0 + wn * 64 + ni * 8 + t * 2;
                if (j < V) {
                    float e0 = expf(c[mi][ni][hf * 2 + 0] + b2[j]);
                    float e1 = expf(c[mi][ni][hf * 2 + 1] + b2[j + 1]);
                    *(float2*)(g_logits + (size_t)r * V + j) = make_float2(e0, e1);
                    ps += e0 + e1;
                }
            }
            ps += __shfl_xor_sync(0xffffffffu, ps, 1);
            ps += __shfl_xor_sync(0xffffffffu, ps, 2);
            if (t == 0) ssum[r * 4 + wn] = ps;
        }
    }
    __syncthreads();
    if (tid < 128) {
        float s2 = ssum[tid * 4] + ssum[tid * 4 + 1] + ssum[tid * 4 + 2] + ssum[tid * 4 + 3];
        atomicAdd(&g_psum[tid], s2);
    }
}

// ---------------------------------------------------------------------------
// K5b: final_dist = expstore / sumexp * gen_p, zero OOV tail.
// ---------------------------------------------------------------------------
__global__ void k5b_final(float* __restrict__ out)
{
    const int i = blockIdx.x * 256 + threadIdx.x;
    if (i >= B * VO) return;
    const int b = i / VO;
    const int c = i - b * VO;
    float v = 0.f;
    if (c < V) {
        const float gp = out[OFF_GP + b];
        v = g_logits[(size_t)b * V + c] * (1.f / g_psum[b]) * gp;
    }
    out[i] = v;
}

__global__ void k5c_scatter(const int* __restrict__ ewo, float* __restrict__ out)
{
    const int i = blockIdx.x * 256 + threadIdx.x;
    if (i >= B * S) return;
    const int b = i / S;
    const float gp = out[OFF_GP + b];
    const float a = out[OFF_AT + i];
    atomicAdd(out + (size_t)b * VO + ewo[i], a * (1.f - gp));
}

// ---------------------------------------------------------------------------
extern "C" void kernel_launch(void* const* d_in, const int* in_sizes, int n_in,
                              void* d_out, int out_size)
{
    const int*   idx      = (const int*)  d_in[0];
    const float* h0       = (const float*)d_in[1];
    const float* c0       = (const float*)d_in[2];
    const float* EO       = (const float*)d_in[3];
    const int*   emask    = (const int*)  d_in[4];
    const float* ctxv     = (const float*)d_in[5];
    const int*   ewo      = (const int*)  d_in[7];
    const float* coverage = (const float*)d_in[8];
    const float* emb      = (const float*)d_in[9];
    const float* Wi       = (const float*)d_in[10];
    const float* bi       = (const float*)d_in[11];
    const float* W_ih     = (const float*)d_in[12];
    const float* W_hh     = (const float*)d_in[13];
    const float* b_ih     = (const float*)d_in[14];
    const float* b_hh     = (const float*)d_in[15];
    const float* att_wh   = (const float*)d_in[16];
    const float* att_ws   = (const float*)d_in[17];
    const float* att_wc   = (const float*)d_in[18];
    const float* att_bc   = (const float*)d_in[19];
    const float* att_v    = (const float*)d_in[20];
    const float* gp_wh    = (const float*)d_in[21];
    const float* gp_bh    = (const float*)d_in[22];
    const float* gp_ws    = (const float*)d_in[23];
    const float* gp_bs    = (const float*)d_in[24];
    const float* gp_wx    = (const float*)d_in[25];
    const float* gp_bx    = (const float*)d_in[26];
    const float* out_w1   = (const float*)d_in[27];
    const float* out_b1   = (const float*)d_in[28];
    const float* out_w2   = (const float*)d_in[29];
    const float* out_b2   = (const float*)d_in[30];
    float* out = (float*)d_out;

    static int attr_done = 0;
    if (!attr_done) {
        cudaFuncSetAttribute(k2_mma, cudaFuncAttributeMaxDynamicSharedMemorySize, K2_SMEM);
        cudaFuncSetAttribute(k4_mma, cudaFuncAttributeMaxDynamicSharedMemorySize, K4_SMEM);
        attr_done = 1;
    }

    k0_wh<<<512, 256>>>(att_wh);
    k1_lstm<<<B, 256>>>(idx, h0, c0, ctxv, emb, Wi, bi, W_ih, W_hh, b_ih, b_hh,
                        att_ws, att_bc, gp_ws, gp_bs, gp_wx, gp_bx, gp_bh, out);
    k2_mma<<<(B * S) / 64, 512, K2_SMEM>>>(EO, att_wc, att_v, coverage, emask);
    k3a_softmax<<<B, 512>>>(coverage, out);
    k3c_ctxpart<<<B * 4, 512>>>(EO, out);
    k3d_ctx<<<B, 512>>>(gp_wh, out);
    {
        dim3 g3b(4, 2);
        k3b_hidden<<<g3b, 256>>>(out_w1, out_b1, out);
    }
    k4_mma<<<(V + 255) / 256, 512, K4_SMEM>>>(out_w2, out_b2);
    k5b_final<<<(B * VO + 255) / 256, 256>>>(out);
    k5c_scatter<<<(B * S + 255) / 256, 256>>>(ewo, out);
}

// round 12
// speedup vs baseline: 2.1560x; 1.6559x over previous
#include <cuda_runtime.h>
#include <cuda_fp16.h>
#include <math.h>

#define B 128
#define S 400
#define H 256
#define E 128
#define V 50000
#define OOV 50
#define TWOH 512
#define VO (V + OOV)

#define OFF_HT   (B * VO)
#define OFF_CT   (OFF_HT + B * H)
#define OFF_CTX  (OFF_CT + B * H)
#define OFF_AT   (OFF_CTX + B * TWOH)
#define OFF_GP   (OFF_AT + B * S)
#define OFF_COV  (OFF_GP + B)

__device__ float g_decbase[B * TWOH];
__device__ float g_gpart[B];
__device__ float g_et[B * S];
__device__ float g_hidden[B * H];
__device__ float g_logits[(size_t)B * V];   // holds exp(logit) after k4
__device__ float g_psum[B];
__device__ float g_ctxpart[B * 8 * TWOH];
__device__ float g_x[B * E];
__device__ float g_gates[B * 4 * H];
__device__ float g_status[B * TWOH];
// Wh pre-packed fp16 hi, k-pair packed, chunked: [16 chunks][512 n][16 kp]
__device__ unsigned g_WhHi[16 * 512 * 16];

__device__ __forceinline__ float sigf(float x) { return 1.0f / (1.0f + expf(-x)); }

__device__ __forceinline__ unsigned packhi(float x, float y) {
    __half hx = __float2half_rn(x), hy = __float2half_rn(y);
    return ((unsigned)__half_as_ushort(hy) << 16) | (unsigned)__half_as_ushort(hx);
}

__device__ __forceinline__ void mma16(float c[4], const unsigned a[4], unsigned b0, unsigned b1) {
    asm("mma.sync.aligned.m16n8k16.row.col.f32.f16.f16.f32 "
        "{%0,%1,%2,%3}, {%4,%5,%6,%7}, {%8,%9}, {%0,%1,%2,%3};"
        : "+f"(c[0]), "+f"(c[1]), "+f"(c[2]), "+f"(c[3])
        : "r"(a[0]), "r"(a[1]), "r"(a[2]), "r"(a[3]), "r"(b0), "r"(b1));
}

// ---------------------------------------------------------------------------
// K0: pre-pack Wh fp16 hi, k-pair packed; zero g_psum. grid=(512), 256thr.
// ---------------------------------------------------------------------------
__global__ void k0_wh(const float* __restrict__ Wh)
{
    int idx = blockIdx.x * 256 + threadIdx.x;
    int n = idx >> 8;
    int kpg = idx & 255;
    int k = kpg * 2;
    int c = k >> 5, kp = (k & 31) >> 1;
    float2 v = *(const float2*)(Wh + (size_t)n * TWOH + k);
    g_WhHi[(c * 512 + n) * 16 + kp] = packhi(v.x, v.y);
    if (blockIdx.x == 0 && threadIdx.x < B) g_psum[threadIdx.x] = 0.f;
}

// ---------------------------------------------------------------------------
// Generic 64x64 SIMT GEMM body used by the k1*/k3b family (inlined per kernel).
// 256 thr: rl=tid>>2 (tile row for loads), kq=tid&3; compute 16x16 thr grid, 4x4.
// ---------------------------------------------------------------------------

// k1a: x = Wi @ [ctx, emb] + bi.  M=128, N=128, K=640. grid=(2,2), 256thr.
__global__ void k1a_x(
    const int* __restrict__ idxv, const float* __restrict__ ctxv,
    const float* __restrict__ emb, const float* __restrict__ Wi,
    const float* __restrict__ bi)
{
    __shared__ __align__(16) float As[16][68];
    __shared__ __align__(16) float Ws[16][68];
    const int tid = threadIdx.x;
    const int tx = tid & 15, ty = tid >> 4;
    const int rl = tid >> 2, kq = tid & 3;
    const int m0 = blockIdx.y * 64, n0 = blockIdx.x * 64;

    float acc[4][4];
    #pragma unroll
    for (int a = 0; a < 4; a++)
        #pragma unroll
        for (int c = 0; c < 4; c++) acc[a][c] = 0.f;

    for (int kt = 0; kt < 40; kt++) {
        const int k = kt * 16 + kq * 4;
        const int m = m0 + rl;
        float4 av = (k < TWOH)
            ? *(const float4*)(ctxv + (size_t)m * TWOH + k)
            : *(const float4*)(emb + (size_t)idxv[m] * E + (k - TWOH));
        float4 wv = *(const float4*)(Wi + (size_t)(n0 + rl) * (TWOH + E) + k);
        __syncthreads();
        As[kq * 4 + 0][rl] = av.x; As[kq * 4 + 1][rl] = av.y;
        As[kq * 4 + 2][rl] = av.z; As[kq * 4 + 3][rl] = av.w;
        Ws[kq * 4 + 0][rl] = wv.x; Ws[kq * 4 + 1][rl] = wv.y;
        Ws[kq * 4 + 2][rl] = wv.z; Ws[kq * 4 + 3][rl] = wv.w;
        __syncthreads();
        #pragma unroll
        for (int kk = 0; kk < 16; kk++) {
            float ar[4], wr[4];
            *(float4*)ar = *(const float4*)&As[kk][ty * 4];
            *(float4*)wr = *(const float4*)&Ws[kk][tx * 4];
            #pragma unroll
            for (int mi = 0; mi < 4; mi++)
                #pragma unroll
                for (int jj = 0; jj < 4; jj++)
                    acc[mi][jj] += ar[mi] * wr[jj];
        }
    }
    #pragma unroll
    for (int mi = 0; mi < 4; mi++) {
        const int m = m0 + ty * 4 + mi;
        #pragma unroll
        for (int jj = 0; jj < 4; jj++) {
            const int o = n0 + tx * 4 + jj;
            g_x[m * E + o] = acc[mi][jj] + bi[o];
        }
    }
}

// k1b: gates = [x|h0] @ [W_ih|W_hh].T + biases. M=128, N=1024, K=384. grid=(16,2).
__global__ void k1b_gates(
    const float* __restrict__ h0,
    const float* __restrict__ W_ih, const float* __restrict__ W_hh,
    const float* __restrict__ b_ih, const float* __restrict__ b_hh)
{
    __shared__ __align__(16) float As[16][68];
    __shared__ __align__(16) float Ws[16][68];
    const int tid = threadIdx.x;
    const int tx = tid & 15, ty = tid >> 4;
    const int rl = tid >> 2, kq = tid & 3;
    const int m0 = blockIdx.y * 64, n0 = blockIdx.x * 64;

    float acc[4][4];
    #pragma unroll
    for (int a = 0; a < 4; a++)
        #pragma unroll
        for (int c = 0; c < 4; c++) acc[a][c] = 0.f;

    for (int kt = 0; kt < 24; kt++) {
        const int k = kt * 16 + kq * 4;
        const int m = m0 + rl;
        const int n = n0 + rl;
        float4 av = (k < E)
            ? *(const float4*)(g_x + (size_t)m * E + k)
            : *(const float4*)(h0 + (size_t)m * H + (k - E));
        float4 wv = (k < E)
            ? *(const float4*)(W_ih + (size_t)n * E + k)
            : *(const float4*)(W_hh + (size_t)n * H + (k - E));
        __syncthreads();
        As[kq * 4 + 0][rl] = av.x; As[kq * 4 + 1][rl] = av.y;
        As[kq * 4 + 2][rl] = av.z; As[kq * 4 + 3][rl] = av.w;
        Ws[kq * 4 + 0][rl] = wv.x; Ws[kq * 4 + 1][rl] = wv.y;
        Ws[kq * 4 + 2][rl] = wv.z; Ws[kq * 4 + 3][rl] = wv.w;
        __syncthreads();
        #pragma unroll
        for (int kk = 0; kk < 16; kk++) {
            float ar[4], wr[4];
            *(float4*)ar = *(const float4*)&As[kk][ty * 4];
            *(float4*)wr = *(const float4*)&Ws[kk][tx * 4];
            #pragma unroll
            for (int mi = 0; mi < 4; mi++)
                #pragma unroll
                for (int jj = 0; jj < 4; jj++)
                    acc[mi][jj] += ar[mi] * wr[jj];
        }
    }
    #pragma unroll
    for (int mi = 0; mi < 4; mi++) {
        const int m = m0 + ty * 4 + mi;
        #pragma unroll
        for (int jj = 0; jj < 4; jj++) {
            const int o = n0 + tx * 4 + jj;
            g_gates[m * 4 * H + o] = acc[mi][jj] + b_ih[o] + b_hh[o];
        }
    }
}

// k1b2: LSTM pointwise. grid=(B), 256thr (one thread per h).
__global__ void k1b2_lstm(const float* __restrict__ c0, float* __restrict__ out)
{
    const int b = blockIdx.x, t = threadIdx.x;
    const float* gr = g_gates + (size_t)b * 4 * H;
    float ig = sigf(gr[t]);
    float fg = sigf(gr[H + t]);
    float gg = tanhf(gr[2 * H + t]);
    float og = sigf(gr[3 * H + t]);
    float c = fg * c0[b * H + t] + ig * gg;
    float h = og * tanhf(c);
    out[OFF_HT + b * H + t] = h;
    out[OFF_CT + b * H + t] = c;
    g_status[b * TWOH + t] = h;
    g_status[b * TWOH + H + t] = c;
}

// k1c: decbase = status @ att_ws.T + att_bc. M=128, N=512, K=512. grid=(8,2).
__global__ void k1c_decbase(
    const float* __restrict__ att_ws, const float* __restrict__ att_bc)
{
    __shared__ __align__(16) float As[16][68];
    __shared__ __align__(16) float Ws[16][68];
    const int tid = threadIdx.x;
    const int tx = tid & 15, ty = tid >> 4;
    const int rl = tid >> 2, kq = tid & 3;
    const int m0 = blockIdx.y * 64, n0 = blockIdx.x * 64;

    float acc[4][4];
    #pragma unroll
    for (int a = 0; a < 4; a++)
        #pragma unroll
        for (int c = 0; c < 4; c++) acc[a][c] = 0.f;

    for (int kt = 0; kt < 32; kt++) {
        const int k = kt * 16 + kq * 4;
        float4 av = *(const float4*)(g_status + (size_t)(m0 + rl) * TWOH + k);
        float4 wv = *(const float4*)(att_ws + (size_t)(n0 + rl) * TWOH + k);
        __syncthreads();
        As[kq * 4 + 0][rl] = av.x; As[kq * 4 + 1][rl] = av.y;
        As[kq * 4 + 2][rl] = av.z; As[kq * 4 + 3][rl] = av.w;
        Ws[kq * 4 + 0][rl] = wv.x; Ws[kq * 4 + 1][rl] = wv.y;
        Ws[kq * 4 + 2][rl] = wv.z; Ws[kq * 4 + 3][rl] = wv.w;
        __syncthreads();
        #pragma unroll
        for (int kk = 0; kk < 16; kk++) {
            float ar[4], wr[4];
            *(float4*)ar = *(const float4*)&As[kk][ty * 4];
            *(float4*)wr = *(const float4*)&Ws[kk][tx * 4];
            #pragma unroll
            for (int mi = 0; mi < 4; mi++)
                #pragma unroll
                for (int jj = 0; jj < 4; jj++)
                    acc[mi][jj] += ar[mi] * wr[jj];
        }
    }
    #pragma unroll
    for (int mi = 0; mi < 4; mi++) {
        const int m = m0 + ty * 4 + mi;
        #pragma unroll
        for (int jj = 0; jj < 4; jj++) {
            const int o = n0 + tx * 4 + jj;
            g_decbase[m * TWOH + o] = acc[mi][jj] + att_bc[o];
        }
    }
}

// k1d: gen_p partial. grid=(B), 256thr.
__global__ void k1d_gp(
    const float* __restrict__ gp_ws, const float* __restrict__ gp_bs,
    const float* __restrict__ gp_wx, const float* __restrict__ gp_bx,
    const float* __restrict__ gp_bh)
{
    const int b = blockIdx.x, t = threadIdx.x;
    __shared__ float red[256];
    float p = gp_ws[t] * g_status[b * TWOH + t]
            + gp_ws[256 + t] * g_status[b * TWOH + 256 + t];
    if (t < E) p += gp_wx[t] * g_x[b * E + t];
    red[t] = p;
    __syncthreads();
    for (int off = 128; off > 0; off >>= 1) {
        if (t < off) red[t] += red[t + off];
        __syncthreads();
    }
    if (t == 0) g_gpart[b] = red[0] + gp_bs[0] + gp_bx[0] + gp_bh[0];
}

// ---------------------------------------------------------------------------
// K2: attention scores, SINGLE-product fp16 mma (fp32 acc), double-buffered
// register-prefetch pipeline. (frozen from R10/R11)
// ---------------------------------------------------------------------------
#define K2P 20
#define K2_AH 0
#define K2_BH 5120
#define K2_BUF 46080
#define K2_SV  92160
#define K2_SWC 94208
#define K2_SDB 96256
#define K2_EP  100352
#define K2_SMEM 102400

__global__ void __launch_bounds__(512, 1) k2_mma(
    const float* __restrict__ EO,
    const float* __restrict__ att_wc, const float* __restrict__ att_v,
    const float* __restrict__ coverage, const int* __restrict__ mask)
{
    extern __shared__ char smem[];
    float* sv  = (float*)(smem + K2_SV);
    float* swc = (float*)(smem + K2_SWC);
    float* sdb = (float*)(smem + K2_SDB);
    float* ep  = (float*)(smem + K2_EP);

    const int tid = threadIdx.x;
    const int w = tid >> 5, lane = tid & 31;
    const int g = lane >> 2, t = lane & 3;
    const int wm = w & 1, wn = w >> 1;
    const int row0 = blockIdx.x * 64;
    const int b0 = row0 / S;
    const int b1e = (row0 + 63) / S;

    sv[tid] = att_v[tid];
    swc[tid] = att_wc[tid];
    sdb[tid] = g_decbase[b0 * TWOH + tid];
    sdb[512 + tid] = g_decbase[b1e * TWOH + tid];

    const int ar = tid >> 3, aq = tid & 7;
    const int bn = tid >> 2, bkq = tid & 3;
    const float* aptr = EO + (size_t)(row0 + ar) * TWOH + aq * 4;

    float c[2][8][4];
    #pragma unroll
    for (int mi = 0; mi < 2; mi++)
        #pragma unroll
        for (int ni = 0; ni < 8; ni++)
            #pragma unroll
            for (int q = 0; q < 4; q++) c[mi][ni][q] = 0.f;

    float4 av;
    uint4 bv[4];

    av = *(const float4*)(aptr);
    #pragma unroll
    for (int i = 0; i < 4; i++)
        bv[i] = *(const uint4*)(g_WhHi + ((size_t)(i * 128 + bn) * 16 + bkq * 4));
    {
        *(uint2*)((unsigned*)(smem + K2_AH) + ar * K2P + aq * 2) =
            make_uint2(packhi(av.x, av.y), packhi(av.z, av.w));
        unsigned* BHp = (unsigned*)(smem + K2_BH);
        #pragma unroll
        for (int i = 0; i < 4; i++)
            *(uint4*)(BHp + (i * 128 + bn) * K2P + bkq * 4) = bv[i];
    }
    __syncthreads();

    for (int kt = 0; kt < 16; kt++) {
        char* bufc = smem + (kt & 1) * K2_BUF;
        if (kt < 15) {
            av = *(const float4*)(aptr + (kt + 1) * 32);
            #pragma unroll
            for (int i = 0; i < 4; i++)
                bv[i] = *(const uint4*)(g_WhHi + ((size_t)((kt + 1) * 512 + i * 128 + bn) * 16 + bkq * 4));
        }

        unsigned* AHc = (unsigned*)(bufc + K2_AH);
        unsigned* BHc = (unsigned*)(bufc + K2_BH);
        #pragma unroll
        for (int s = 0; s < 2; s++) {
            unsigned ah[2][4];
            #pragma unroll
            for (int mi = 0; mi < 2; mi++) {
                const unsigned* pa = AHc + (wm * 32 + mi * 16 + g) * K2P + s * 8 + t;
                ah[mi][0] = pa[0]; ah[mi][1] = pa[8 * K2P];
                ah[mi][2] = pa[4]; ah[mi][3] = pa[8 * K2P + 4];
            }
            #pragma unroll
            for (int ni = 0; ni < 8; ni++) {
                const unsigned* pb = BHc + (wn * 64 + ni * 8 + g) * K2P + s * 8 + t;
                unsigned bh0 = pb[0], bh1 = pb[4];
                #pragma unroll
                for (int mi = 0; mi < 2; mi++)
                    mma16(c[mi][ni], ah[mi], bh0, bh1);
            }
        }

        if (kt < 15) {
            char* bufn = smem + ((kt + 1) & 1) * K2_BUF;
            *(uint2*)((unsigned*)(bufn + K2_AH) + ar * K2P + aq * 2) =
                make_uint2(packhi(av.x, av.y), packhi(av.z, av.w));
            unsigned* BHn = (unsigned*)(bufn + K2_BH);
            #pragma unroll
            for (int i = 0; i < 4; i++)
                *(uint4*)(BHn + (i * 128 + bn) * K2P + bkq * 4) = bv[i];
        }
        __syncthreads();
    }

    #pragma unroll
    for (int mi = 0; mi < 2; mi++) {
        #pragma unroll
        for (int hf = 0; hf < 2; hf++) {
            const int rl = wm * 32 + mi * 16 + hf * 8 + g;
            const int r = row0 + rl;
            const int dbo = (r / S != b0) ? 512 : 0;
            const float cov = coverage[r];
            float acc = 0.f;
            #pragma unroll
            for (int ni = 0; ni < 8; ni++) {
                const int j = wn * 64 + ni * 8 + t * 2;
                float v0 = c[mi][ni][hf * 2 + 0] + sdb[dbo + j] + cov * swc[j];
                float v1 = c[mi][ni][hf * 2 + 1] + sdb[dbo + j + 1] + cov * swc[j + 1];
                acc += sv[j] * tanhf(v0) + sv[j + 1] * tanhf(v1);
            }
            acc += __shfl_xor_sync(0xffffffffu, acc, 1);
            acc += __shfl_xor_sync(0xffffffffu, acc, 2);
            if (t == 0) ep[rl * 8 + wn] = acc;
        }
    }
    __syncthreads();
    if (tid < 64) {
        float sacc = 0.f;
        #pragma unroll
        for (int q = 0; q < 8; q++) sacc += ep[tid * 8 + q];
        const int r = row0 + tid;
        g_et[r] = (mask[r] == 0) ? -1e30f : sacc;
    }
}

// ---------------------------------------------------------------------------
// K3a: masked softmax over S -> a_t, next_coverage. grid=(B), 512thr.
// ---------------------------------------------------------------------------
__global__ void k3a_softmax(const float* __restrict__ coverage, float* __restrict__ out)
{
    const int b = blockIdx.x;
    const int t = threadIdx.x;
    __shared__ float red[512];

    float e = (t < S) ? g_et[b * S + t] : -1e30f;
    red[t] = e;
    __syncthreads();
    for (int off = 256; off > 0; off >>= 1) {
        if (t < off) red[t] = fmaxf(red[t], red[t + off]);
        __syncthreads();
    }
    const float mx = red[0];
    __syncthreads();

    float ex = (t < S) ? expf(e - mx) : 0.f;
    red[t] = ex;
    __syncthreads();
    for (int off = 256; off > 0; off >>= 1) {
        if (t < off) red[t] += red[t + off];
        __syncthreads();
    }
    const float inv = 1.f / red[0];

    if (t < S) {
        float a = ex * inv;
        out[OFF_AT + b * S + t] = a;
        out[OFF_COV + b * S + t] = coverage[b * S + t] + a;
    }
}

// ---------------------------------------------------------------------------
// K3c: ctx partials, 8-way s-split. grid=(B*8), 512thr.
// ---------------------------------------------------------------------------
__global__ void k3c_ctxpart(const float* __restrict__ EO, const float* __restrict__ out)
{
    const int blk = blockIdx.x;
    const int b = blk >> 3, q = blk & 7;
    const int t = threadIdx.x;
    __shared__ float sa[50];
    if (t < 50) sa[t] = out[OFF_AT + b * S + q * 50 + t];
    __syncthreads();
    const float* eob = EO + ((size_t)b * S + q * 50) * TWOH;
    float c = 0.f;
    #pragma unroll 10
    for (int s = 0; s < 50; s++) c += sa[s] * eob[(size_t)s * TWOH + t];
    g_ctxpart[(size_t)blk * TWOH + t] = c;
}

// ---------------------------------------------------------------------------
// K3d: combine ctx partials + gen_p. grid=(B), 512thr.
// ---------------------------------------------------------------------------
__global__ void k3d_ctx(const float* __restrict__ gp_wh, float* __restrict__ out)
{
    const int b = blockIdx.x;
    const int t = threadIdx.x;
    __shared__ float red[512];
    float c = 0.f;
    #pragma unroll
    for (int q = 0; q < 8; q++)
        c += g_ctxpart[(size_t)(b * 8 + q) * TWOH + t];
    out[OFF_CTX + b * TWOH + t] = c;
    red[t] = gp_wh[t] * c;
    __syncthreads();
    for (int off = 256; off > 0; off >>= 1) {
        if (t < off) red[t] += red[t + off];
        __syncthreads();
    }
    if (t == 0) out[OFF_GP + b] = sigf(red[0] + g_gpart[b]);
}

// ---------------------------------------------------------------------------
// K3b: hidden = relu(out_w1 @ [h_t, ctx] + b1), tiled 64x64. grid=(4,2), 256thr.
// ---------------------------------------------------------------------------
__global__ void k3b_hidden(
    const float* __restrict__ out_w1, const float* __restrict__ out_b1,
    const float* __restrict__ out)
{
    __shared__ __align__(16) float As[16][68];
    __shared__ __align__(16) float Ws[16][68];

    const int tid = threadIdx.x;
    const int tx = tid & 15, ty = tid >> 4;
    const int rl = tid >> 2, kq = tid & 3;
    const int m0 = blockIdx.y * 64;
    const int n0 = blockIdx.x * 64;

    float acc[4][4];
    #pragma unroll
    for (int a = 0; a < 4; a++)
        #pragma unroll
        for (int c = 0; c < 4; c++) acc[a][c] = 0.f;

    for (int kt = 0; kt < 48; kt++) {
        const int k = kt * 16 + kq * 4;
        const int m = m0 + rl;
        float4 av = (k < H)
            ? *(const float4*)(out + OFF_HT + m * H + k)
            : *(const float4*)(out + OFF_CTX + m * TWOH + (k - H));
        float4 wv = *(const float4*)(out_w1 + (size_t)(n0 + rl) * (H + TWOH) + k);
        __syncthreads();
        As[kq * 4 + 0][rl] = av.x; As[kq * 4 + 1][rl] = av.y;
        As[kq * 4 + 2][rl] = av.z; As[kq * 4 + 3][rl] = av.w;
        Ws[kq * 4 + 0][rl] = wv.x; Ws[kq * 4 + 1][rl] = wv.y;
        Ws[kq * 4 + 2][rl] = wv.z; Ws[kq * 4 + 3][rl] = wv.w;
        __syncthreads();
        #pragma unroll
        for (int kk = 0; kk < 16; kk++) {
            float ar[4], wr[4];
            *(float4*)ar = *(const float4*)&As[kk][ty * 4];
            *(float4*)wr = *(const float4*)&Ws[kk][tx * 4];
            #pragma unroll
            for (int mi = 0; mi < 4; mi++)
                #pragma unroll
                for (int jj = 0; jj < 4; jj++)
                    acc[mi][jj] += ar[mi] * wr[jj];
        }
    }

    #pragma unroll
    for (int mi = 0; mi < 4; mi++) {
        const int m = m0 + ty * 4 + mi;
        #pragma unroll
        for (int jj = 0; jj < 4; jj++) {
            const int o = n0 + tx * 4 + jj;
            g_hidden[m * H + o] = fmaxf(acc[mi][jj] + out_b1[o], 0.f);
        }
    }
}

// ---------------------------------------------------------------------------
// K4: logits GEMM, single-product fp16 mma; epilogue stores exp(logit) and
// accumulates per-row vocab sum-exp. (frozen from R11)
// ---------------------------------------------------------------------------
#define K4_AH 0
#define K4_BH 10240
#define K4_BUF 30720
#define K4_SMEM 61440

__global__ void __launch_bounds__(512, 1) k4_mma(
    const float* __restrict__ W2, const float* __restrict__ b2)
{
    extern __shared__ char smem[];

    const int tid = threadIdx.x;
    const int w = tid >> 5, lane = tid & 31;
    const int g = lane >> 2, t = lane & 3;
    const int wm = w & 3, wn = w >> 2;
    const int j0 = blockIdx.x * 256;

    const int ar = tid >> 3, aq = tid & 7;
    const int br = tid >> 3, bq = tid & 7;

    float c[2][8][4];
    #pragma unroll
    for (int mi = 0; mi < 2; mi++)
        #pragma unroll
        for (int ni = 0; ni < 8; ni++)
            #pragma unroll
            for (int q = 0; q < 4; q++) c[mi][ni][q] = 0.f;

    float4 avv[2], bvv[4];

    #pragma unroll
    for (int i = 0; i < 2; i++)
        avv[i] = *(const float4*)(g_hidden + (size_t)(i * 64 + ar) * H + aq * 4);
    #pragma unroll
    for (int i = 0; i < 4; i++) {
        int j = j0 + i * 64 + br;
        bvv[i] = (j < V) ? *(const float4*)(W2 + (size_t)j * H + bq * 4)
                         : make_float4(0.f, 0.f, 0.f, 0.f);
    }
    {
        unsigned* AHp = (unsigned*)(smem + K4_AH);
        unsigned* BHp = (unsigned*)(smem + K4_BH);
        #pragma unroll
        for (int i = 0; i < 2; i++)
            *(uint2*)(AHp + (i * 64 + ar) * K2P + aq * 2) =
                make_uint2(packhi(avv[i].x, avv[i].y), packhi(avv[i].z, avv[i].w));
        #pragma unroll
        for (int i = 0; i < 4; i++)
            *(uint2*)(BHp + (i * 64 + br) * K2P + bq * 2) =
                make_uint2(packhi(bvv[i].x, bvv[i].y), packhi(bvv[i].z, bvv[i].w));
    }
    __syncthreads();

    for (int kt = 0; kt < 8; kt++) {
        char* bufc = smem + (kt & 1) * K4_BUF;
        if (kt < 7) {
            const int k0 = (kt + 1) * 32;
            #pragma unroll
            for (int i = 0; i < 2; i++)
                avv[i] = *(const float4*)(g_hidden + (size_t)(i * 64 + ar) * H + k0 + aq * 4);
            #pragma unroll
            for (int i = 0; i < 4; i++) {
                int j = j0 + i * 64 + br;
                bvv[i] = (j < V) ? *(const float4*)(W2 + (size_t)j * H + k0 + bq * 4)
                                 : make_float4(0.f, 0.f, 0.f, 0.f);
            }
        }

        unsigned* AHc = (unsigned*)(bufc + K4_AH);
        unsigned* BHc = (unsigned*)(bufc + K4_BH);
        #pragma unroll
        for (int s = 0; s < 2; s++) {
            unsigned ah[2][4];
            #pragma unroll
            for (int mi = 0; mi < 2; mi++) {
                const unsigned* pa = AHc + (wm * 32 + mi * 16 + g) * K2P + s * 8 + t;
                ah[mi][0] = pa[0]; ah[mi][1] = pa[8 * K2P];
                ah[mi][2] = pa[4]; ah[mi][3] = pa[8 * K2P + 4];
            }
            #pragma unroll
            for (int ni = 0; ni < 8; ni++) {
                const unsigned* pb = BHc + (wn * 64 + ni * 8 + g) * K2P + s * 8 + t;
                unsigned bh0 = pb[0], bh1 = pb[4];
                #pragma unroll
                for (int mi = 0; mi < 2; mi++)
                    mma16(c[mi][ni], ah[mi], bh0, bh1);
            }
        }

        if (kt < 7) {
            char* bufn = smem + ((kt + 1) & 1) * K4_BUF;
            unsigned* AHn = (unsigned*)(bufn + K4_AH);
            unsigned* BHn = (unsigned*)(bufn + K4_BH);
            #pragma unroll
            for (int i = 0; i < 2; i++)
                *(uint2*)(AHn + (i * 64 + ar) * K2P + aq * 2) =
                    make_uint2(packhi(avv[i].x, avv[i].y), packhi(avv[i].z, avv[i].w));
            #pragma unroll
            for (int i = 0; i < 4; i++)
                *(uint2*)(BHn + (i * 64 + br) * K2P + bq * 2) =
                    make_uint2(packhi(bvv[i].x, bvv[i].y), packhi(bvv[i].z, bvv[i].w));
        }
        __syncthreads();
    }

    // epilogue: store exp(logit) + per-row partial sum-exp
    float* ssum = (float*)smem;
    #pragma unroll
    for (int mi = 0; mi < 2; mi++) {
        #pragma unroll
        for (int hf = 0; hf < 2; hf++) {
            const int r = wm * 32 + mi * 16 + hf * 8 + g;
            float ps = 0.f;
            #pragma unroll
            for (int ni = 0; ni < 8; ni++) {
                const int j = j0 + wn * 64 + ni * 8 + t * 2;
                if (j < V) {
                    float e0 = expf(c[mi][ni][hf * 2 + 0] + b2[j]);
                    float e1 = expf(c[mi][ni][hf * 2 + 1] + b2[j + 1]);
                    *(float2*)(g_logits + (size_t)r * V + j) = make_float2(e0, e1);
                    ps += e0 + e1;
                }
            }
            ps += __shfl_xor_sync(0xffffffffu, ps, 1);
            ps += __shfl_xor_sync(0xffffffffu, ps, 2);
            if (t == 0) ssum[r * 4 + wn] = ps;
        }
    }
    __syncthreads();
    if (tid < 128) {
        float s2 = ssum[tid * 4] + ssum[tid * 4 + 1] + ssum[tid * 4 + 2] + ssum[tid * 4 + 3];
        atomicAdd(&g_psum[tid], s2);
    }
}

// ---------------------------------------------------------------------------
__global__ void k5b_final(float* __restrict__ out)
{
    const int i = blockIdx.x * 256 + threadIdx.x;
    if (i >= B * VO) return;
    const int b = i / VO;
    const int c = i - b * VO;
    float v = 0.f;
    if (c < V) {
        const float gp = out[OFF_GP + b];
        v = g_logits[(size_t)b * V + c] * (1.f / g_psum[b]) * gp;
    }
    out[i] = v;
}

__global__ void k5c_scatter(const int* __restrict__ ewo, float* __restrict__ out)
{
    const int i = blockIdx.x * 256 + threadIdx.x;
    if (i >= B * S) return;
    const int b = i / S;
    const float gp = out[OFF_GP + b];
    const float a = out[OFF_AT + i];
    atomicAdd(out + (size_t)b * VO + ewo[i], a * (1.f - gp));
}

// ---------------------------------------------------------------------------
extern "C" void kernel_launch(void* const* d_in, const int* in_sizes, int n_in,
                              void* d_out, int out_size)
{
    const int*   idx      = (const int*)  d_in[0];
    const float* h0       = (const float*)d_in[1];
    const float* c0       = (const float*)d_in[2];
    const float* EO       = (const float*)d_in[3];
    const int*   emask    = (const int*)  d_in[4];
    const float* ctxv     = (const float*)d_in[5];
    const int*   ewo      = (const int*)  d_in[7];
    const float* coverage = (const float*)d_in[8];
    const float* emb      = (const float*)d_in[9];
    const float* Wi       = (const float*)d_in[10];
    const float* bi       = (const float*)d_in[11];
    const float* W_ih     = (const float*)d_in[12];
    const float* W_hh     = (const float*)d_in[13];
    const float* b_ih     = (const float*)d_in[14];
    const float* b_hh     = (const float*)d_in[15];
    const float* att_wh   = (const float*)d_in[16];
    const float* att_ws   = (const float*)d_in[17];
    const float* att_wc   = (const float*)d_in[18];
    const float* att_bc   = (const float*)d_in[19];
    const float* att_v    = (const float*)d_in[20];
    const float* gp_wh    = (const float*)d_in[21];
    const float* gp_bh    = (const float*)d_in[22];
    const float* gp_ws    = (const float*)d_in[23];
    const float* gp_bs    = (const float*)d_in[24];
    const float* gp_wx    = (const float*)d_in[25];
    const float* gp_bx    = (const float*)d_in[26];
    const float* out_w1   = (const float*)d_in[27];
    const float* out_b1   = (const float*)d_in[28];
    const float* out_w2   = (const float*)d_in[29];
    const float* out_b2   = (const float*)d_in[30];
    float* out = (float*)d_out;

    static int attr_done = 0;
    if (!attr_done) {
        cudaFuncSetAttribute(k2_mma, cudaFuncAttributeMaxDynamicSharedMemorySize, K2_SMEM);
        cudaFuncSetAttribute(k4_mma, cudaFuncAttributeMaxDynamicSharedMemorySize, K4_SMEM);
        attr_done = 1;
    }

    k0_wh<<<512, 256>>>(att_wh);
    {
        dim3 ga(2, 2);
        k1a_x<<<ga, 256>>>(idx, ctxv, emb, Wi, bi);
        dim3 gb(16, 2);
        k1b_gates<<<gb, 256>>>(h0, W_ih, W_hh, b_ih, b_hh);
        k1b2_lstm<<<B, 256>>>(c0, out);
        dim3 gc(8, 2);
        k1c_decbase<<<gc, 256>>>(att_ws, att_bc);
        k1d_gp<<<B, 256>>>(gp_ws, gp_bs, gp_wx, gp_bx, gp_bh);
    }
    k2_mma<<<(B * S) / 64, 512, K2_SMEM>>>(EO, att_wc, att_v, coverage, emask);
    k3a_softmax<<<B, 512>>>(coverage, out);
    k3c_ctxpart<<<B * 8, 512>>>(EO, out);
    k3d_ctx<<<B, 512>>>(gp_wh, out);
    {
        dim3 g3b(4, 2);
        k3b_hidden<<<g3b, 256>>>(out_w1, out_b1, out);
    }
    k4_mma<<<(V + 255) / 256, 512, K4_SMEM>>>(out_w2, out_b2);
    k5b_final<<<(B * VO + 255) / 256, 256>>>(out);
    k5c_scatter<<<(B * S + 255) / 256, 256>>>(ewo, out);
}